// round 1
// baseline (speedup 1.0000x reference)
#include <cuda_runtime.h>
#include <math.h>

// Problem constants
#define BATCH   2
#define C1      64          // x1/x2 channels, also OUT_CH
#define IN_CH   128         // concat channels
#define OFF_CH  256         // 2*IN_CH offset channels
#define OUT_CH  64
#define H1      128
#define W1      128
#define H       256         // 2*H1
#define W       256
#define HW      (H*W)       // 65536
#define BN_EPS  1e-5f
#define BN_N    ((float)(BATCH*H*W))   // 131072

// ---------------- scratch (device globals; no allocation allowed) -------------
__device__ float g_xcat[(size_t)BATCH * IN_CH * HW];    // 67 MB
__device__ float g_off [(size_t)BATCH * OFF_CH * HW];   // 134 MB
__device__ float g_xd  [(size_t)BATCH * IN_CH * HW];    // 67 MB
__device__ float g_pre1[(size_t)BATCH * OUT_CH * HW];   // 33.5 MB
__device__ float g_stats[4 * OUT_CH];   // sum1, sq1, sum2, sq2
__device__ float g_bn   [4 * OUT_CH];   // scale1, shift1, scale2, shift2

// ---------------- kernel 0: zero stats ---------------------------------------
__global__ void init_stats_kernel() {
    g_stats[threadIdx.x] = 0.f;
}

// ---------------- kernel 1: ConvTranspose2d(2,2,s=2) + concat ----------------
// xcat[b, 0:64]  = x2[b]
// xcat[b, 64+o, Y, X] = up_b[o] + sum_i x1[b,i,Y/2,X/2] * up_w[i,o,Y&1,X&1]
__global__ void upcat_kernel(const float* __restrict__ x1,
                             const float* __restrict__ x2,
                             const float* __restrict__ up_w,
                             const float* __restrict__ up_b) {
    size_t idx = (size_t)blockIdx.x * blockDim.x + threadIdx.x;
    if (idx >= (size_t)BATCH * IN_CH * HW) return;
    int x = idx & (W - 1);
    int y = (idx >> 8) & (H - 1);
    int c = (int)(idx >> 16) & (IN_CH - 1);
    int b = (int)(idx >> 16) / IN_CH;
    if (c < C1) {
        g_xcat[idx] = x2[((size_t)(b * C1 + c) * H + y) * W + x];
    } else {
        int o = c - C1;
        int ys = y >> 1, xs = x >> 1, ky = y & 1, kx = x & 1;
        const float* xp = x1 + (size_t)b * C1 * H1 * W1 + ys * W1 + xs;
        const float* wp = up_w + (o * 2 + ky) * 2 + kx;
        float acc = up_b[o];
        #pragma unroll 8
        for (int i = 0; i < C1; ++i)
            acc = fmaf(xp[(size_t)i * (H1 * W1)], wp[(size_t)i * (C1 * 4)], acc);
        g_xcat[idx] = acc;
    }
}

// ---------------- kernel 2/4/6: tiled direct 3x3 conv, pad=1 ------------------
// MODE 0: plain (no bias)      -> g_off
// MODE 1: +bias, +BN stats     -> g_pre1
// MODE 2: input gets BN+ReLU (scale1/shift1) applied on load, +bias, +stats -> out
template <int IC, int OC, int MODE>
__global__ __launch_bounds__(256, 4)
void conv3x3_kernel(const float* __restrict__ in, const float* __restrict__ wgt,
                    const float* __restrict__ bias, float* __restrict__ out,
                    const float* __restrict__ bnsc, const float* __restrict__ bnsh,
                    float* __restrict__ st_sum, float* __restrict__ st_sq) {
    // block: (32,8) threads, tile = 32x8 pixels x 16 OC
    __shared__ float s_in[4][10][34];
    __shared__ float s_w[4][16][12];

    const int tx = threadIdx.x, ty = threadIdx.y;
    const int tid = ty * 32 + tx;
    const int tile = blockIdx.x;            // 0..255
    const int tx0 = (tile & 7) * 32;
    const int ty0 = (tile >> 3) * 8;
    const int ocb = blockIdx.y;             // OC/16 groups
    const int b = blockIdx.z;

    float acc[16];
    #pragma unroll
    for (int oc = 0; oc < 16; ++oc)
        acc[oc] = (MODE >= 1) ? bias[ocb * 16 + oc] : 0.f;

    for (int icc = 0; icc < IC / 4; ++icc) {
        // load input tile (4 ic x 10 x 34), zero-padded at borders
        for (int l = tid; l < 4 * 10 * 34; l += 256) {
            int ic_l = l / 340;
            int rem = l - ic_l * 340;
            int iy = rem / 34;
            int ix = rem - iy * 34;
            int gy = ty0 + iy - 1, gx = tx0 + ix - 1;
            float v = 0.f;
            if (gy >= 0 && gy < H && gx >= 0 && gx < W) {
                int icg = icc * 4 + ic_l;
                v = in[((size_t)b * IC + icg) * HW + gy * W + gx];
                if (MODE == 2)
                    v = fmaxf(fmaf(v, bnsc[icg], bnsh[icg]), 0.f);
            }
            (&s_in[0][0][0])[l] = v;
        }
        // load weights (16 oc x 4 ic x 9), tap-padded to 12
        for (int l = tid; l < 4 * 16 * 9; l += 256) {
            int tap = l % 9;
            int t2 = l / 9;
            int ic_l = t2 & 3;
            int oc_l = t2 >> 2;
            s_w[ic_l][oc_l][tap] =
                wgt[((size_t)(ocb * 16 + oc_l) * IC + icc * 4 + ic_l) * 9 + tap];
        }
        __syncthreads();

        #pragma unroll
        for (int ic_l = 0; ic_l < 4; ++ic_l) {
            float r0 = s_in[ic_l][ty + 0][tx + 0];
            float r1 = s_in[ic_l][ty + 0][tx + 1];
            float r2 = s_in[ic_l][ty + 0][tx + 2];
            float r3 = s_in[ic_l][ty + 1][tx + 0];
            float r4 = s_in[ic_l][ty + 1][tx + 1];
            float r5 = s_in[ic_l][ty + 1][tx + 2];
            float r6 = s_in[ic_l][ty + 2][tx + 0];
            float r7 = s_in[ic_l][ty + 2][tx + 1];
            float r8 = s_in[ic_l][ty + 2][tx + 2];
            #pragma unroll
            for (int oc = 0; oc < 16; ++oc) {
                float4 wa = *reinterpret_cast<const float4*>(&s_w[ic_l][oc][0]);
                float4 wb = *reinterpret_cast<const float4*>(&s_w[ic_l][oc][4]);
                float w8 = s_w[ic_l][oc][8];
                float a = acc[oc];
                a = fmaf(r0, wa.x, a);
                a = fmaf(r1, wa.y, a);
                a = fmaf(r2, wa.z, a);
                a = fmaf(r3, wa.w, a);
                a = fmaf(r4, wb.x, a);
                a = fmaf(r5, wb.y, a);
                a = fmaf(r6, wb.z, a);
                a = fmaf(r7, wb.w, a);
                a = fmaf(r8, w8, a);
                acc[oc] = a;
            }
        }
        __syncthreads();
    }

    // write + optional per-channel stats
    const int y = ty0 + ty, x = tx0 + tx;
    const size_t ob = ((size_t)b * OC + ocb * 16) * HW + (size_t)y * W + x;
    #pragma unroll
    for (int oc = 0; oc < 16; ++oc)
        out[ob + (size_t)oc * HW] = acc[oc];

    if (MODE >= 1) {
        #pragma unroll
        for (int oc = 0; oc < 16; ++oc) {
            float s = acc[oc];
            float q = s * s;
            #pragma unroll
            for (int o = 16; o; o >>= 1) {
                s += __shfl_xor_sync(0xffffffffu, s, o);
                q += __shfl_xor_sync(0xffffffffu, q, o);
            }
            if ((tid & 31) == 0) {
                atomicAdd(&st_sum[ocb * 16 + oc], s);
                atomicAdd(&st_sq[ocb * 16 + oc], q);
            }
        }
    }
}

// ---------------- kernel 3: deformable bilinear gather ------------------------
__global__ void gather_kernel() {
    size_t idx = (size_t)blockIdx.x * blockDim.x + threadIdx.x;
    if (idx >= (size_t)BATCH * IN_CH * HW) return;
    int x = idx & (W - 1);
    int y = (idx >> 8) & (H - 1);
    int c = (int)(idx >> 16) & (IN_CH - 1);
    int b = (int)(idx >> 16) / IN_CH;

    const float* ob = g_off + (size_t)b * OFF_CH * HW;
    size_t flat = 2 * ((size_t)c * HW + (size_t)y * W + x);
    float oy = ob[flat];
    float ox = ob[flat + 1];
    float cy = fminf(fmaxf(oy + (float)y, 0.f), (float)(H - 1));
    float cx = fminf(fmaxf(ox + (float)x, 0.f), (float)(W - 1));
    float y0f = floorf(cy), x0f = floorf(cx);
    int y0 = (int)y0f;
    int y1 = (int)ceilf(cy);
    int x0 = (int)x0f;
    int x1 = (int)ceilf(cx);
    const float* xp = g_xcat + ((size_t)b * IN_CH + c) * HW;
    float v00 = xp[y0 * W + x0];
    float v10 = xp[y1 * W + x0];
    float v01 = xp[y0 * W + x1];
    float v11 = xp[y1 * W + x1];
    float wy = cy - y0f, wx = cx - x0f;
    float vt = fmaf(v10 - v00, wy, v00);
    float vb = fmaf(v11 - v01, wy, v01);
    g_xd[idx] = fmaf(vb - vt, wx, vt);
}

// ---------------- kernel 5/7: BN finalize -------------------------------------
__global__ void bnfin_kernel(const float* __restrict__ sum, const float* __restrict__ sq,
                             const float* __restrict__ g, const float* __restrict__ bb,
                             float* __restrict__ scale, float* __restrict__ shift) {
    int c = threadIdx.x;
    float m = sum[c] / BN_N;
    float v = sq[c] / BN_N - m * m;
    float inv = rsqrtf(v + BN_EPS);
    float sc = g[c] * inv;
    scale[c] = sc;
    shift[c] = bb[c] - m * sc;
}

// ---------------- kernel 8: in-place BN + ReLU on output ----------------------
__global__ void final_bnrelu_kernel(float* __restrict__ out,
                                    const float* __restrict__ scale,
                                    const float* __restrict__ shift) {
    size_t idx = (size_t)blockIdx.x * blockDim.x + threadIdx.x;
    if (idx >= (size_t)BATCH * OUT_CH * HW) return;
    int c = (int)(idx >> 16) & (OUT_CH - 1);
    out[idx] = fmaxf(fmaf(out[idx], scale[c], shift[c]), 0.f);
}

// ---------------- launch ------------------------------------------------------
extern "C" void kernel_launch(void* const* d_in, const int* in_sizes, int n_in,
                              void* d_out, int out_size) {
    const float* x1   = (const float*)d_in[0];
    const float* x2   = (const float*)d_in[1];
    const float* up_w = (const float*)d_in[2];
    const float* up_b = (const float*)d_in[3];
    const float* off_w= (const float*)d_in[4];
    const float* c1_w = (const float*)d_in[5];
    const float* c1_b = (const float*)d_in[6];
    const float* g1   = (const float*)d_in[7];
    const float* b1   = (const float*)d_in[8];
    const float* c2_w = (const float*)d_in[9];
    const float* c2_b = (const float*)d_in[10];
    const float* g2   = (const float*)d_in[11];
    const float* b2   = (const float*)d_in[12];
    float* out = (float*)d_out;

    float *xcat, *off, *xd, *pre1, *stats, *bn;
    cudaGetSymbolAddress((void**)&xcat,  g_xcat);
    cudaGetSymbolAddress((void**)&off,   g_off);
    cudaGetSymbolAddress((void**)&xd,    g_xd);
    cudaGetSymbolAddress((void**)&pre1,  g_pre1);
    cudaGetSymbolAddress((void**)&stats, g_stats);
    cudaGetSymbolAddress((void**)&bn,    g_bn);

    float* sum1 = stats;            float* sq1 = stats + 64;
    float* sum2 = stats + 128;      float* sq2 = stats + 192;
    float* sc1 = bn;                float* sh1 = bn + 64;
    float* sc2 = bn + 128;          float* sh2 = bn + 192;

    init_stats_kernel<<<1, 256>>>();

    {
        size_t n = (size_t)BATCH * IN_CH * HW;
        upcat_kernel<<<(unsigned)((n + 255) / 256), 256>>>(x1, x2, up_w, up_b);
    }

    {
        dim3 grid(256, OFF_CH / 16, BATCH), blk(32, 8);
        conv3x3_kernel<IN_CH, OFF_CH, 0><<<grid, blk>>>(
            xcat, off_w, nullptr, off, nullptr, nullptr, nullptr, nullptr);
    }

    {
        size_t n = (size_t)BATCH * IN_CH * HW;
        gather_kernel<<<(unsigned)((n + 255) / 256), 256>>>();
    }

    {
        dim3 grid(256, OUT_CH / 16, BATCH), blk(32, 8);
        conv3x3_kernel<IN_CH, OUT_CH, 1><<<grid, blk>>>(
            xd, c1_w, c1_b, pre1, nullptr, nullptr, sum1, sq1);
    }

    bnfin_kernel<<<1, 64>>>(sum1, sq1, g1, b1, sc1, sh1);

    {
        dim3 grid(256, OUT_CH / 16, BATCH), blk(32, 8);
        conv3x3_kernel<OUT_CH, OUT_CH, 2><<<grid, blk>>>(
            pre1, c2_w, c2_b, out, sc1, sh1, sum2, sq2);
    }

    bnfin_kernel<<<1, 64>>>(sum2, sq2, g2, b2, sc2, sh2);

    {
        size_t n = (size_t)BATCH * OUT_CH * HW;
        final_bnrelu_kernel<<<(unsigned)((n + 255) / 256), 256>>>(out, sc2, sh2);
    }
}

// round 2
// speedup vs baseline: 1.0351x; 1.0351x over previous
#include <cuda_runtime.h>
#include <math.h>

// Problem constants
#define BATCH   2
#define C1      64
#define IN_CH   128
#define OFF_CH  256
#define OUT_CH  64
#define H1      128
#define W1      128
#define H       256
#define W       256
#define HW      (H*W)
#define BN_EPS  1e-5f
#define BN_N    ((float)(BATCH*H*W))

// ---------------- scratch ----------------------------------------------------
__device__ float g_xcat[(size_t)BATCH * IN_CH * HW];
__device__ float g_off [(size_t)BATCH * OFF_CH * HW];
__device__ float g_xd  [(size_t)BATCH * IN_CH * HW];
__device__ float g_pre1[(size_t)BATCH * OUT_CH * HW];
__device__ float g_stats[4 * OUT_CH];
__device__ float g_bn   [4 * OUT_CH];

// packed f32x2 helpers
__device__ __forceinline__ unsigned long long pk2(float lo, float hi) {
    unsigned long long r;
    asm("mov.b64 %0, {%1, %2};" : "=l"(r) : "f"(lo), "f"(hi));
    return r;
}
__device__ __forceinline__ void unpk2(unsigned long long v, float& lo, float& hi) {
    asm("mov.b64 {%0, %1}, %2;" : "=f"(lo), "=f"(hi) : "l"(v));
}
#define FMA2(d, a, b, c) \
    asm("fma.rn.f32x2 %0, %1, %2, %3;" : "=l"(d) : "l"(a), "l"(b), "l"(c))

// ---------------- kernel 0 ----------------------------------------------------
__global__ void init_stats_kernel() {
    g_stats[threadIdx.x] = 0.f;
}

// ---------------- kernel 1: ConvTranspose2d(2,2,s=2) + concat ----------------
__global__ void upcat_kernel(const float* __restrict__ x1,
                             const float* __restrict__ x2,
                             const float* __restrict__ up_w,
                             const float* __restrict__ up_b) {
    size_t idx = (size_t)blockIdx.x * blockDim.x + threadIdx.x;
    if (idx >= (size_t)BATCH * IN_CH * HW) return;
    int x = idx & (W - 1);
    int y = (idx >> 8) & (H - 1);
    int c = (int)(idx >> 16) & (IN_CH - 1);
    int b = (int)(idx >> 16) / IN_CH;
    if (c < C1) {
        g_xcat[idx] = x2[((size_t)(b * C1 + c) * H + y) * W + x];
    } else {
        int o = c - C1;
        int ys = y >> 1, xs = x >> 1, ky = y & 1, kx = x & 1;
        const float* xp = x1 + (size_t)b * C1 * H1 * W1 + ys * W1 + xs;
        const float* wp = up_w + (o * 2 + ky) * 2 + kx;
        float acc = up_b[o];
        #pragma unroll 8
        for (int i = 0; i < C1; ++i)
            acc = fmaf(xp[(size_t)i * (H1 * W1)], wp[(size_t)i * (C1 * 4)], acc);
        g_xcat[idx] = acc;
    }
}

// ---------------- tiled 3x3 conv with packed f32x2 (2 pixels/thread) ----------
// block (32,8): tile = 64x8 pixels x 16 OC. Each thread: 2 adjacent pixels.
// MODE 0: plain -> out
// MODE 1: +bias, +BN stats
// MODE 2: input BN+ReLU on load, +bias, +stats
template <int IC, int OC, int MODE>
__global__ __launch_bounds__(256, 2)
void conv3x3_kernel(const float* __restrict__ in, const float* __restrict__ wgt,
                    const float* __restrict__ bias, float* __restrict__ out,
                    const float* __restrict__ bnsc, const float* __restrict__ bnsh,
                    float* __restrict__ st_sum, float* __restrict__ st_sq) {
    __shared__ __align__(16) float  s_in[4][10][66];   // 10.3 KB
    __shared__ __align__(16) float2 s_w[4][16][10];    // 5.1 KB (weights duplicated)

    const int tx = threadIdx.x, ty = threadIdx.y;
    const int tid = ty * 32 + tx;
    const int tile = blockIdx.x;            // 0..127
    const int tx0 = (tile & 3) * 64;
    const int ty0 = (tile >> 2) * 8;
    const int ocb = blockIdx.y;
    const int b = blockIdx.z;

    unsigned long long acc[16];
    #pragma unroll
    for (int oc = 0; oc < 16; ++oc) {
        float bv = (MODE >= 1) ? bias[ocb * 16 + oc] : 0.f;
        acc[oc] = pk2(bv, bv);
    }

    for (int icc = 0; icc < IC / 4; ++icc) {
        // input tile: 4 ic x 10 rows x 66 cols, zero-padded borders
        for (int l = tid; l < 4 * 10 * 66; l += 256) {
            int ic_l = l / 660;
            int rem = l - ic_l * 660;
            int iy = rem / 66;
            int ix = rem - iy * 66;
            int gy = ty0 + iy - 1, gx = tx0 + ix - 1;
            float v = 0.f;
            if (gy >= 0 && gy < H && gx >= 0 && gx < W) {
                int icg = icc * 4 + ic_l;
                v = in[((size_t)b * IC + icg) * HW + gy * W + gx];
                if (MODE == 2)
                    v = fmaxf(fmaf(v, bnsc[icg], bnsh[icg]), 0.f);
            }
            (&s_in[0][0][0])[l] = v;
        }
        // weights duplicated into both f32x2 halves
        for (int l = tid; l < 4 * 16 * 9; l += 256) {
            int tap = l % 9;
            int t2 = l / 9;
            int ic_l = t2 & 3;
            int oc_l = t2 >> 2;
            float wv = wgt[((size_t)(ocb * 16 + oc_l) * IC + icc * 4 + ic_l) * 9 + tap];
            s_w[ic_l][oc_l][tap] = make_float2(wv, wv);
        }
        __syncthreads();

        #pragma unroll
        for (int ic_l = 0; ic_l < 4; ++ic_l) {
            // packed taps: pair t = {col 2tx+t, col 2tx+t+1}
            unsigned long long p[9];
            #pragma unroll
            for (int r = 0; r < 3; ++r) {
                float2 a = *reinterpret_cast<const float2*>(&s_in[ic_l][ty + r][2 * tx]);
                float2 q = *reinterpret_cast<const float2*>(&s_in[ic_l][ty + r][2 * tx + 2]);
                p[r * 3 + 0] = pk2(a.x, a.y);
                p[r * 3 + 1] = pk2(a.y, q.x);
                p[r * 3 + 2] = pk2(q.x, q.y);
            }
            #pragma unroll
            for (int oc = 0; oc < 16; ++oc) {
                const ulonglong2* wr =
                    reinterpret_cast<const ulonglong2*>(&s_w[ic_l][oc][0]);
                ulonglong2 w01 = wr[0];
                ulonglong2 w23 = wr[1];
                ulonglong2 w45 = wr[2];
                ulonglong2 w67 = wr[3];
                unsigned long long w8 =
                    *reinterpret_cast<const unsigned long long*>(&s_w[ic_l][oc][8]);
                unsigned long long a = acc[oc];
                FMA2(a, p[0], w01.x, a);
                FMA2(a, p[1], w01.y, a);
                FMA2(a, p[2], w23.x, a);
                FMA2(a, p[3], w23.y, a);
                FMA2(a, p[4], w45.x, a);
                FMA2(a, p[5], w45.y, a);
                FMA2(a, p[6], w67.x, a);
                FMA2(a, p[7], w67.y, a);
                FMA2(a, p[8], w8, a);
                acc[oc] = a;
            }
        }
        __syncthreads();
    }

    const int y = ty0 + ty;
    const int x0 = tx0 + 2 * tx;
    const size_t ob = ((size_t)b * OC + ocb * 16) * HW + (size_t)y * W + x0;
    #pragma unroll
    for (int oc = 0; oc < 16; ++oc) {
        float lo, hi;
        unpk2(acc[oc], lo, hi);
        *reinterpret_cast<float2*>(&out[ob + (size_t)oc * HW]) = make_float2(lo, hi);
    }

    if (MODE >= 1) {
        #pragma unroll
        for (int oc = 0; oc < 16; ++oc) {
            float lo, hi;
            unpk2(acc[oc], lo, hi);
            float s = lo + hi;
            float q = lo * lo + hi * hi;
            #pragma unroll
            for (int o = 16; o; o >>= 1) {
                s += __shfl_xor_sync(0xffffffffu, s, o);
                q += __shfl_xor_sync(0xffffffffu, q, o);
            }
            if ((tid & 31) == 0) {
                atomicAdd(&st_sum[ocb * 16 + oc], s);
                atomicAdd(&st_sq[ocb * 16 + oc], q);
            }
        }
    }
}

// ---------------- kernel 3: deformable bilinear gather ------------------------
__global__ void gather_kernel() {
    size_t idx = (size_t)blockIdx.x * blockDim.x + threadIdx.x;
    if (idx >= (size_t)BATCH * IN_CH * HW) return;
    int x = idx & (W - 1);
    int y = (idx >> 8) & (H - 1);
    int c = (int)(idx >> 16) & (IN_CH - 1);
    int b = (int)(idx >> 16) / IN_CH;

    const float* ob = g_off + (size_t)b * OFF_CH * HW;
    size_t flat = 2 * ((size_t)c * HW + (size_t)y * W + x);
    float oy = ob[flat];
    float ox = ob[flat + 1];
    float cy = fminf(fmaxf(oy + (float)y, 0.f), (float)(H - 1));
    float cx = fminf(fmaxf(ox + (float)x, 0.f), (float)(W - 1));
    float y0f = floorf(cy), x0f = floorf(cx);
    int y0 = (int)y0f;
    int y1 = (int)ceilf(cy);
    int x0 = (int)x0f;
    int x1 = (int)ceilf(cx);
    const float* xp = g_xcat + ((size_t)b * IN_CH + c) * HW;
    float v00 = xp[y0 * W + x0];
    float v10 = xp[y1 * W + x0];
    float v01 = xp[y0 * W + x1];
    float v11 = xp[y1 * W + x1];
    float wy = cy - y0f, wx = cx - x0f;
    float vt = fmaf(v10 - v00, wy, v00);
    float vb = fmaf(v11 - v01, wy, v01);
    g_xd[idx] = fmaf(vb - vt, wx, vt);
}

// ---------------- BN finalize -------------------------------------------------
__global__ void bnfin_kernel(const float* __restrict__ sum, const float* __restrict__ sq,
                             const float* __restrict__ g, const float* __restrict__ bb,
                             float* __restrict__ scale, float* __restrict__ shift) {
    int c = threadIdx.x;
    float m = sum[c] / BN_N;
    float v = sq[c] / BN_N - m * m;
    float inv = rsqrtf(v + BN_EPS);
    float sc = g[c] * inv;
    scale[c] = sc;
    shift[c] = bb[c] - m * sc;
}

// ---------------- in-place BN + ReLU on output --------------------------------
__global__ void final_bnrelu_kernel(float* __restrict__ out,
                                    const float* __restrict__ scale,
                                    const float* __restrict__ shift) {
    size_t idx = (size_t)blockIdx.x * blockDim.x + threadIdx.x;
    if (idx >= (size_t)BATCH * OUT_CH * HW) return;
    int c = (int)(idx >> 16) & (OUT_CH - 1);
    out[idx] = fmaxf(fmaf(out[idx], scale[c], shift[c]), 0.f);
}

// ---------------- launch ------------------------------------------------------
extern "C" void kernel_launch(void* const* d_in, const int* in_sizes, int n_in,
                              void* d_out, int out_size) {
    const float* x1   = (const float*)d_in[0];
    const float* x2   = (const float*)d_in[1];
    const float* up_w = (const float*)d_in[2];
    const float* up_b = (const float*)d_in[3];
    const float* off_w= (const float*)d_in[4];
    const float* c1_w = (const float*)d_in[5];
    const float* c1_b = (const float*)d_in[6];
    const float* g1   = (const float*)d_in[7];
    const float* b1   = (const float*)d_in[8];
    const float* c2_w = (const float*)d_in[9];
    const float* c2_b = (const float*)d_in[10];
    const float* g2   = (const float*)d_in[11];
    const float* b2   = (const float*)d_in[12];
    float* out = (float*)d_out;

    float *xcat, *off, *xd, *pre1, *stats, *bn;
    cudaGetSymbolAddress((void**)&xcat,  g_xcat);
    cudaGetSymbolAddress((void**)&off,   g_off);
    cudaGetSymbolAddress((void**)&xd,    g_xd);
    cudaGetSymbolAddress((void**)&pre1,  g_pre1);
    cudaGetSymbolAddress((void**)&stats, g_stats);
    cudaGetSymbolAddress((void**)&bn,    g_bn);

    float* sum1 = stats;            float* sq1 = stats + 64;
    float* sum2 = stats + 128;      float* sq2 = stats + 192;
    float* sc1 = bn;                float* sh1 = bn + 64;
    float* sc2 = bn + 128;          float* sh2 = bn + 192;

    init_stats_kernel<<<1, 256>>>();

    {
        size_t n = (size_t)BATCH * IN_CH * HW;
        upcat_kernel<<<(unsigned)((n + 255) / 256), 256>>>(x1, x2, up_w, up_b);
    }

    {
        dim3 grid(128, OFF_CH / 16, BATCH), blk(32, 8);
        conv3x3_kernel<IN_CH, OFF_CH, 0><<<grid, blk>>>(
            xcat, off_w, nullptr, off, nullptr, nullptr, nullptr, nullptr);
    }

    {
        size_t n = (size_t)BATCH * IN_CH * HW;
        gather_kernel<<<(unsigned)((n + 255) / 256), 256>>>();
    }

    {
        dim3 grid(128, OUT_CH / 16, BATCH), blk(32, 8);
        conv3x3_kernel<IN_CH, OUT_CH, 1><<<grid, blk>>>(
            xd, c1_w, c1_b, pre1, nullptr, nullptr, sum1, sq1);
    }

    bnfin_kernel<<<1, 64>>>(sum1, sq1, g1, b1, sc1, sh1);

    {
        dim3 grid(128, OUT_CH / 16, BATCH), blk(32, 8);
        conv3x3_kernel<OUT_CH, OUT_CH, 2><<<grid, blk>>>(
            pre1, c2_w, c2_b, out, sc1, sh1, sum2, sq2);
    }

    bnfin_kernel<<<1, 64>>>(sum2, sq2, g2, b2, sc2, sh2);

    {
        size_t n = (size_t)BATCH * OUT_CH * HW;
        final_bnrelu_kernel<<<(unsigned)((n + 255) / 256), 256>>>(out, sc2, sh2);
    }
}

// round 4
// speedup vs baseline: 3.0203x; 2.9178x over previous
#include <cuda_runtime.h>
#include <cuda_bf16.h>
#include <math.h>
#include <stdint.h>

// Problem constants
#define BATCH   2
#define C1      64
#define IN_CH   128
#define OFF_CH  256
#define OUT_CH  64
#define H1      128
#define W1      128
#define H       256
#define W       256
#define HW      (H*W)
#define BN_EPS  1e-5f
#define BN_N    ((float)(BATCH*H*W))

// ---------------- scratch ----------------------------------------------------
__device__ float g_xcat[(size_t)BATCH * IN_CH * HW];
__device__ float g_off [(size_t)BATCH * OFF_CH * HW];
__device__ float g_xd  [(size_t)BATCH * IN_CH * HW];
__device__ float g_pre1[(size_t)BATCH * OUT_CH * HW];
__device__ float g_stats[4 * OUT_CH];
__device__ float g_bn   [4 * OUT_CH];

// packed bf16 hi/lo weight planes, layout [tap][icc][oc][ic%32]
__device__ __nv_bfloat16 g_wb_off_hi[9 * 4 * OFF_CH * 32];
__device__ __nv_bfloat16 g_wb_off_lo[9 * 4 * OFF_CH * 32];
__device__ __nv_bfloat16 g_wb_c1_hi [9 * 4 * OUT_CH * 32];
__device__ __nv_bfloat16 g_wb_c1_lo [9 * 4 * OUT_CH * 32];
__device__ __nv_bfloat16 g_wb_c2_hi [9 * 2 * OUT_CH * 32];
__device__ __nv_bfloat16 g_wb_c2_lo [9 * 2 * OUT_CH * 32];

// ---------------- PTX helpers --------------------------------------------------
__device__ __forceinline__ uint32_t smem_u32(const void* p) {
    uint32_t a;
    asm("{ .reg .u64 t; cvta.to.shared.u64 t, %1; cvt.u32.u64 %0, t; }"
        : "=r"(a) : "l"(p));
    return a;
}
__device__ __forceinline__ void ldmx4(uint32_t* r, uint32_t a) {
    asm volatile("ldmatrix.sync.aligned.m8n8.x4.shared.b16 {%0,%1,%2,%3}, [%4];"
        : "=r"(r[0]), "=r"(r[1]), "=r"(r[2]), "=r"(r[3]) : "r"(a));
}
__device__ __forceinline__ void ldmx2(uint32_t* r, uint32_t a) {
    asm volatile("ldmatrix.sync.aligned.m8n8.x2.shared.b16 {%0,%1}, [%2];"
        : "=r"(r[0]), "=r"(r[1]) : "r"(a));
}
__device__ __forceinline__ void mma_bf16(float* d, const uint32_t* A, const uint32_t* B) {
    asm volatile(
        "mma.sync.aligned.m16n8k16.row.col.f32.bf16.bf16.f32 "
        "{%0,%1,%2,%3}, {%4,%5,%6,%7}, {%8,%9}, {%0,%1,%2,%3};"
        : "+f"(d[0]), "+f"(d[1]), "+f"(d[2]), "+f"(d[3])
        : "r"(A[0]), "r"(A[1]), "r"(A[2]), "r"(A[3]), "r"(B[0]), "r"(B[1]));
}
__device__ __forceinline__ uint32_t pack_bf16(float v0, float v1) {
    __nv_bfloat16 h0 = __float2bfloat16(v0);
    __nv_bfloat16 h1 = __float2bfloat16(v1);
    uint16_t u0, u1;
    memcpy(&u0, &h0, 2); memcpy(&u1, &h1, 2);
    return ((uint32_t)u1 << 16) | u0;
}
__device__ __forceinline__ float bf16_hi(float v) {
    return __bfloat162float(__float2bfloat16(v));
}

// ---------------- small kernels -------------------------------------------------
__global__ void init_stats_kernel() { g_stats[threadIdx.x] = 0.f; }

// (OC,IC,3,3) fp32 -> [tap][icc][oc][il] bf16 hi/lo
template <int IC>
__global__ void pack_weights_kernel(const float* __restrict__ w,
                                    __nv_bfloat16* __restrict__ hi,
                                    __nv_bfloat16* __restrict__ lo, int OC) {
    int idx = blockIdx.x * blockDim.x + threadIdx.x;
    int total = 9 * (IC / 32) * OC * 32;
    if (idx >= total) return;
    int il  = idx & 31;
    int oc  = (idx >> 5) % OC;
    int icc = ((idx >> 5) / OC) % (IC / 32);
    int tap = (idx >> 5) / OC / (IC / 32);
    float v = w[((size_t)oc * IC + icc * 32 + il) * 9 + tap];
    __nv_bfloat16 h = __float2bfloat16(v);
    hi[idx] = h;
    lo[idx] = __float2bfloat16(v - __bfloat162float(h));
}

// ---------------- ConvTranspose2d(2,2,s=2) + concat -----------------------------
__global__ void upcat_kernel(const float* __restrict__ x1,
                             const float* __restrict__ x2,
                             const float* __restrict__ up_w,
                             const float* __restrict__ up_b) {
    size_t idx = (size_t)blockIdx.x * blockDim.x + threadIdx.x;
    if (idx >= (size_t)BATCH * IN_CH * HW) return;
    int x = idx & (W - 1);
    int y = (idx >> 8) & (H - 1);
    int c = (int)(idx >> 16) & (IN_CH - 1);
    int b = (int)(idx >> 16) / IN_CH;
    if (c < C1) {
        g_xcat[idx] = x2[((size_t)(b * C1 + c) * H + y) * W + x];
    } else {
        int o = c - C1;
        int ys = y >> 1, xs = x >> 1, ky = y & 1, kx = x & 1;
        const float* xp = x1 + (size_t)b * C1 * H1 * W1 + ys * W1 + xs;
        const float* wp = up_w + (o * 2 + ky) * 2 + kx;
        float acc = up_b[o];
        #pragma unroll 8
        for (int i = 0; i < C1; ++i)
            acc = fmaf(xp[(size_t)i * (H1 * W1)], wp[(size_t)i * (C1 * 4)], acc);
        g_xcat[idx] = acc;
    }
}

// ---------------- bf16 split-K HMMA implicit-GEMM 3x3 conv ----------------------
// Block: M=128 pixels (half image row) x N=64 oc. 8 warps (4m x 2n), warp 32x32.
// Stages = (icc, tap); smem double buffered; A/B bf16 hi+lo planes, rows padded
// to 80B (16B-aligned, bank-spread). 3-term split: ah*bh + ah*bl + al*bh.
// MODE 0: plain. MODE 1: +bias,+stats. MODE 2: BN+ReLU on input, +bias, +stats.
template <int IC, int MODE>
__global__ __launch_bounds__(256, 2)
void conv_hmma_kernel(const float* __restrict__ in,
                      const __nv_bfloat16* __restrict__ wh,
                      const __nv_bfloat16* __restrict__ wl,
                      int OC,
                      const float* __restrict__ bias, float* __restrict__ out,
                      const float* __restrict__ bnsc, const float* __restrict__ bnsh,
                      float* __restrict__ st_sum, float* __restrict__ st_sq) {
    extern __shared__ __align__(128) char smem[];
    constexpr int ICC = IC / 32;
    constexpr int NSTAGE = ICC * 9;
    constexpr int A_LO = 10240, B_HI = 20480, B_LO = 25600, SBUF = 30720;

    const int tid = threadIdx.x, lane = tid & 31, wid = tid >> 5;
    const int wm = wid & 3, wn = wid >> 2;
    const int y  = blockIdx.x >> 1;
    const int x0 = (blockIdx.x & 1) * 128;
    const int b  = blockIdx.z;
    const int oc0 = blockIdx.y * 64;
    const float* inb = in + (size_t)b * IC * HW;
    const uint32_t sb = smem_u32(smem);

    // fill mapping: warp covers 32 pixels, upper/lower 16 ic's
    const int fp  = (wid & 3) * 32 + lane;
    const int fih = wid >> 2;

    float acc[2][4][4];
    #pragma unroll
    for (int mt = 0; mt < 2; ++mt)
        #pragma unroll
        for (int nt = 0; nt < 4; ++nt)
            #pragma unroll
            for (int q = 0; q < 4; ++q) acc[mt][nt][q] = 0.f;

#define FILL(S, BOFS) do {                                                        \
    const int _s = (S); char* _bb = smem + (BOFS);                                \
    int _icc = _s / 9, _tap = _s % 9;                                             \
    int _dy = _tap / 3 - 1, _dx = _tap % 3 - 1;                                   \
    int _ys = y + _dy;                                                            \
    int _xs = x0 + fp + _dx;                                                      \
    bool _ok = (_ys >= 0) && (_ys < H) && (_xs >= 0) && (_xs < W);                \
    long _po = (long)_ys * W + _xs;                                               \
    _Pragma("unroll")                                                             \
    for (int _i = 0; _i < 8; ++_i) {                                              \
        int _icl = fih * 16 + _i * 2;                                             \
        int _ic = _icc * 32 + _icl;                                               \
        float _v0 = 0.f, _v1 = 0.f;                                               \
        if (_ok) {                                                                \
            const float* _sp = inb + (size_t)_ic * HW + _po;                      \
            _v0 = __ldg(_sp);                                                     \
            _v1 = __ldg(_sp + HW);                                                \
            if (MODE == 2) {                                                      \
                _v0 = fmaxf(fmaf(_v0, __ldg(bnsc + _ic), __ldg(bnsh + _ic)), 0.f);\
                _v1 = fmaxf(fmaf(_v1, __ldg(bnsc + _ic + 1),                      \
                                 __ldg(bnsh + _ic + 1)), 0.f);                    \
            }                                                                     \
        }                                                                         \
        uint32_t _hp = pack_bf16(_v0, _v1);                                       \
        uint32_t _lp = pack_bf16(_v0 - bf16_hi(_v0), _v1 - bf16_hi(_v1));         \
        *(uint32_t*)(_bb + fp * 80 + _icl * 2) = _hp;                             \
        *(uint32_t*)(_bb + A_LO + fp * 80 + _icl * 2) = _lp;                      \
    }                                                                             \
    {                                                                             \
        int _wofs = ((_tap * ICC + _icc) * OC + oc0) * 32;                        \
        const uint32_t* _sh = (const uint32_t*)(wh + _wofs);                      \
        const uint32_t* _sl = (const uint32_t*)(wl + _wofs);                      \
        _Pragma("unroll")                                                         \
        for (int _k = 0; _k < 4; ++_k) {                                          \
            int _idx = tid + _k * 256;                                            \
            int _row = _idx >> 4, _col = _idx & 15;                               \
            *(uint32_t*)(_bb + B_HI + _row * 80 + _col * 4) = __ldg(_sh + _idx);  \
            *(uint32_t*)(_bb + B_LO + _row * 80 + _col * 4) = __ldg(_sl + _idx);  \
        }                                                                         \
    }                                                                             \
} while (0)

#define COMPUTE(BOFS) do {                                                        \
    const uint32_t _ab = sb + (BOFS);                                             \
    _Pragma("unroll")                                                             \
    for (int _ks = 0; _ks < 2; ++_ks) {                                           \
        int _kb = _ks * 32;                                                       \
        uint32_t _ah[2][4], _al[2][4], _bh[4][2], _bl[4][2];                      \
        _Pragma("unroll")                                                         \
        for (int _mt = 0; _mt < 2; ++_mt) {                                       \
            uint32_t _a = _ab + (uint32_t)(wm * 32 + _mt * 16 + (lane & 15)) * 80 \
                          + _kb + ((lane >> 4) << 4);                             \
            ldmx4(_ah[_mt], _a);                                                  \
            ldmx4(_al[_mt], _a + A_LO);                                           \
        }                                                                         \
        _Pragma("unroll")                                                         \
        for (int _nt = 0; _nt < 4; ++_nt) {                                       \
            uint32_t _ba = _ab + B_HI                                             \
                          + (uint32_t)(wn * 32 + _nt * 8 + (lane & 7)) * 80       \
                          + _kb + (((lane >> 3) & 1) << 4);                       \
            ldmx2(_bh[_nt], _ba);                                                 \
            ldmx2(_bl[_nt], _ba + (B_LO - B_HI));                                 \
        }                                                                         \
        _Pragma("unroll")                                                         \
        for (int _mt = 0; _mt < 2; ++_mt)                                         \
            _Pragma("unroll")                                                     \
            for (int _nt = 0; _nt < 4; ++_nt) {                                   \
                mma_bf16(acc[_mt][_nt], _ah[_mt], _bh[_nt]);                      \
                mma_bf16(acc[_mt][_nt], _ah[_mt], _bl[_nt]);                      \
                mma_bf16(acc[_mt][_nt], _al[_mt], _bh[_nt]);                      \
            }                                                                     \
    }                                                                             \
} while (0)

    FILL(0, 0);
    __syncthreads();
    for (int s = 0; s < NSTAGE; ++s) {
        COMPUTE((s & 1) * SBUF);
        if (s + 1 < NSTAGE) FILL(s + 1, ((s + 1) & 1) * SBUF);
        __syncthreads();
    }

#undef FILL
#undef COMPUTE

    // ---- epilogue
    float* outb = out + ((size_t)b * OC + oc0) * HW + (size_t)y * W + x0;
    const int rr0 = lane >> 2, cj = (lane & 3) * 2;

    if (MODE == 0) {
        #pragma unroll
        for (int mt = 0; mt < 2; ++mt)
            #pragma unroll
            for (int nt = 0; nt < 4; ++nt)
                #pragma unroll
                for (int q = 0; q < 4; ++q) {
                    int p   = wm * 32 + mt * 16 + rr0 + (q >> 1) * 8;
                    int ocl = wn * 32 + nt * 8 + cj + (q & 1);
                    outb[(size_t)ocl * HW + p] = acc[mt][nt][q];
                }
    } else {
        float ss[8], qq[8];
        #pragma unroll
        for (int i = 0; i < 8; ++i) { ss[i] = 0.f; qq[i] = 0.f; }
        #pragma unroll
        for (int nt = 0; nt < 4; ++nt)
            #pragma unroll
            for (int j = 0; j < 2; ++j) {
                int ocl = wn * 32 + nt * 8 + cj + j;
                float bv = __ldg(bias + oc0 + ocl);
                int idx = nt * 2 + j;
                #pragma unroll
                for (int mt = 0; mt < 2; ++mt)
                    #pragma unroll
                    for (int rr = 0; rr < 2; ++rr) {
                        float v = acc[mt][nt][rr * 2 + j] + bv;
                        int p = wm * 32 + mt * 16 + rr0 + rr * 8;
                        outb[(size_t)ocl * HW + p] = v;
                        ss[idx] += v;
                        qq[idx] += v * v;
                    }
            }
        #pragma unroll
        for (int i = 0; i < 8; ++i) {
            #pragma unroll
            for (int o = 4; o <= 16; o <<= 1) {
                ss[i] += __shfl_xor_sync(0xffffffffu, ss[i], o);
                qq[i] += __shfl_xor_sync(0xffffffffu, qq[i], o);
            }
        }
        if (lane < 4) {
            #pragma unroll
            for (int i = 0; i < 8; ++i) {
                int oc = oc0 + wn * 32 + (i >> 1) * 8 + lane * 2 + (i & 1);
                atomicAdd(&st_sum[oc], ss[i]);
                atomicAdd(&st_sq[oc], qq[i]);
            }
        }
    }
}

// ---------------- deformable bilinear gather -------------------------------------
__global__ void gather_kernel() {
    size_t idx = (size_t)blockIdx.x * blockDim.x + threadIdx.x;
    if (idx >= (size_t)BATCH * IN_CH * HW) return;
    int x = idx & (W - 1);
    int y = (idx >> 8) & (H - 1);
    int c = (int)(idx >> 16) & (IN_CH - 1);
    int b = (int)(idx >> 16) / IN_CH;

    const float* ob = g_off + (size_t)b * OFF_CH * HW;
    size_t flat = 2 * ((size_t)c * HW + (size_t)y * W + x);
    float oy = ob[flat];
    float ox = ob[flat + 1];
    float cy = fminf(fmaxf(oy + (float)y, 0.f), (float)(H - 1));
    float cx = fminf(fmaxf(ox + (float)x, 0.f), (float)(W - 1));
    float y0f = floorf(cy), x0f = floorf(cx);
    int y0 = (int)y0f;
    int y1 = (int)ceilf(cy);
    int x0 = (int)x0f;
    int x1 = (int)ceilf(cx);
    const float* xp = g_xcat + ((size_t)b * IN_CH + c) * HW;
    float v00 = xp[y0 * W + x0];
    float v10 = xp[y1 * W + x0];
    float v01 = xp[y0 * W + x1];
    float v11 = xp[y1 * W + x1];
    float wy = cy - y0f, wx = cx - x0f;
    float vt = fmaf(v10 - v00, wy, v00);
    float vb = fmaf(v11 - v01, wy, v01);
    g_xd[idx] = fmaf(vb - vt, wx, vt);
}

// ---------------- BN finalize -------------------------------------------------
__global__ void bnfin_kernel(const float* __restrict__ sum, const float* __restrict__ sq,
                             const float* __restrict__ g, const float* __restrict__ bb,
                             float* __restrict__ scale, float* __restrict__ shift) {
    int c = threadIdx.x;
    float m = sum[c] / BN_N;
    float v = sq[c] / BN_N - m * m;
    float inv = rsqrtf(v + BN_EPS);
    float sc = g[c] * inv;
    scale[c] = sc;
    shift[c] = bb[c] - m * sc;
}

// ---------------- in-place BN + ReLU on output ---------------------------------
__global__ void final_bnrelu_kernel(float* __restrict__ out,
                                    const float* __restrict__ scale,
                                    const float* __restrict__ shift) {
    size_t idx = (size_t)blockIdx.x * blockDim.x + threadIdx.x;
    if (idx >= (size_t)BATCH * OUT_CH * HW) return;
    int c = (int)(idx >> 16) & (OUT_CH - 1);
    out[idx] = fmaxf(fmaf(out[idx], scale[c], shift[c]), 0.f);
}

// ---------------- launch ---------------------------------------------------------
extern "C" void kernel_launch(void* const* d_in, const int* in_sizes, int n_in,
                              void* d_out, int out_size) {
    const float* x1   = (const float*)d_in[0];
    const float* x2   = (const float*)d_in[1];
    const float* up_w = (const float*)d_in[2];
    const float* up_b = (const float*)d_in[3];
    const float* off_w= (const float*)d_in[4];
    const float* c1_w = (const float*)d_in[5];
    const float* c1_b = (const float*)d_in[6];
    const float* g1   = (const float*)d_in[7];
    const float* b1   = (const float*)d_in[8];
    const float* c2_w = (const float*)d_in[9];
    const float* c2_b = (const float*)d_in[10];
    const float* g2   = (const float*)d_in[11];
    const float* b2   = (const float*)d_in[12];
    float* out = (float*)d_out;

    float *xcat, *off, *xd, *pre1, *stats, *bn;
    __nv_bfloat16 *woh, *wol, *w1h, *w1l, *w2h, *w2l;
    cudaGetSymbolAddress((void**)&xcat,  g_xcat);
    cudaGetSymbolAddress((void**)&off,   g_off);
    cudaGetSymbolAddress((void**)&xd,    g_xd);
    cudaGetSymbolAddress((void**)&pre1,  g_pre1);
    cudaGetSymbolAddress((void**)&stats, g_stats);
    cudaGetSymbolAddress((void**)&bn,    g_bn);
    cudaGetSymbolAddress((void**)&woh,   g_wb_off_hi);
    cudaGetSymbolAddress((void**)&wol,   g_wb_off_lo);
    cudaGetSymbolAddress((void**)&w1h,   g_wb_c1_hi);
    cudaGetSymbolAddress((void**)&w1l,   g_wb_c1_lo);
    cudaGetSymbolAddress((void**)&w2h,   g_wb_c2_hi);
    cudaGetSymbolAddress((void**)&w2l,   g_wb_c2_lo);

    float* sum1 = stats;            float* sq1 = stats + 64;
    float* sum2 = stats + 128;      float* sq2 = stats + 192;
    float* sc1 = bn;                float* sh1 = bn + 64;
    float* sc2 = bn + 128;          float* sh2 = bn + 192;

    const int SMEM = 2 * 30720;   // 61440
    static bool attr_done = false;
    cudaFuncSetAttribute(conv_hmma_kernel<IN_CH, 0>,
                         cudaFuncAttributeMaxDynamicSharedMemorySize, SMEM);
    cudaFuncSetAttribute(conv_hmma_kernel<IN_CH, 1>,
                         cudaFuncAttributeMaxDynamicSharedMemorySize, SMEM);
    cudaFuncSetAttribute(conv_hmma_kernel<OUT_CH, 2>,
                         cudaFuncAttributeMaxDynamicSharedMemorySize, SMEM);
    (void)attr_done;

    // pack weights into bf16 hi/lo planes
    {
        int n0 = 9 * 4 * OFF_CH * 32;
        pack_weights_kernel<IN_CH><<<(n0 + 255) / 256, 256>>>(off_w, woh, wol, OFF_CH);
        int n1 = 9 * 4 * OUT_CH * 32;
        pack_weights_kernel<IN_CH><<<(n1 + 255) / 256, 256>>>(c1_w, w1h, w1l, OUT_CH);
        int n2 = 9 * 2 * OUT_CH * 32;
        pack_weights_kernel<OUT_CH><<<(n2 + 255) / 256, 256>>>(c2_w, w2h, w2l, OUT_CH);
    }

    init_stats_kernel<<<1, 256>>>();

    {
        size_t n = (size_t)BATCH * IN_CH * HW;
        upcat_kernel<<<(unsigned)((n + 255) / 256), 256>>>(x1, x2, up_w, up_b);
    }

    // offset conv: (B,128,H,W) -> (B,256,H,W)
    conv_hmma_kernel<IN_CH, 0><<<dim3(512, OFF_CH / 64, BATCH), 256, SMEM>>>(
        xcat, woh, wol, OFF_CH, nullptr, off, nullptr, nullptr, nullptr, nullptr);

    {
        size_t n = (size_t)BATCH * IN_CH * HW;
        gather_kernel<<<(unsigned)((n + 255) / 256), 256>>>();
    }

    // conv1: (B,128,H,W) -> (B,64,H,W), bias + stats
    conv_hmma_kernel<IN_CH, 1><<<dim3(512, 1, BATCH), 256, SMEM>>>(
        xd, w1h, w1l, OUT_CH, c1_b, pre1, nullptr, nullptr, sum1, sq1);

    bnfin_kernel<<<1, 64>>>(sum1, sq1, g1, b1, sc1, sh1);

    // conv2: BN+ReLU on input, (B,64,H,W) -> (B,64,H,W), bias + stats
    conv_hmma_kernel<OUT_CH, 2><<<dim3(512, 1, BATCH), 256, SMEM>>>(
        pre1, w2h, w2l, OUT_CH, c2_b, out, sc1, sh1, sum2, sq2);

    bnfin_kernel<<<1, 64>>>(sum2, sq2, g2, b2, sc2, sh2);

    {
        size_t n = (size_t)BATCH * OUT_CH * HW;
        final_bnrelu_kernel<<<(unsigned)((n + 255) / 256), 256>>>(out, sc2, sh2);
    }
}

// round 5
// speedup vs baseline: 4.2654x; 1.4123x over previous
#include <cuda_runtime.h>
#include <cuda_bf16.h>
#include <math.h>
#include <stdint.h>

// Problem constants
#define BATCH   2
#define C1      64
#define IN_CH   128
#define OFF_CH  256
#define OUT_CH  64
#define H1      128
#define W1      128
#define H       256
#define W       256
#define HW      (H*W)
#define BN_EPS  1e-5f
#define BN_N    ((float)(BATCH*H*W))

// ---------------- scratch ------------------------------------------------------
__device__ float g_xcat[(size_t)BATCH * IN_CH * HW];
__device__ float g_off [(size_t)BATCH * OFF_CH * HW];
__device__ float g_pre1[(size_t)BATCH * OUT_CH * HW];
__device__ float g_stats[4 * OUT_CH];
__device__ float g_bn   [4 * OUT_CH];

// NHWC bf16 hi/lo planes ([b][pix][ic], ic contiguous)
__device__ __nv_bfloat16 g_xc_h[(size_t)BATCH * HW * IN_CH];
__device__ __nv_bfloat16 g_xc_l[(size_t)BATCH * HW * IN_CH];
__device__ __nv_bfloat16 g_xd_h[(size_t)BATCH * HW * IN_CH];
__device__ __nv_bfloat16 g_xd_l[(size_t)BATCH * HW * IN_CH];
__device__ __nv_bfloat16 g_p1_h[(size_t)BATCH * HW * OUT_CH];
__device__ __nv_bfloat16 g_p1_l[(size_t)BATCH * HW * OUT_CH];

// packed weights [tap][oc][ic] bf16 hi/lo
__device__ __nv_bfloat16 g_w_off_h[9 * OFF_CH * IN_CH];
__device__ __nv_bfloat16 g_w_off_l[9 * OFF_CH * IN_CH];
__device__ __nv_bfloat16 g_w_c1_h [9 * OUT_CH * IN_CH];
__device__ __nv_bfloat16 g_w_c1_l [9 * OUT_CH * IN_CH];
__device__ __nv_bfloat16 g_w_c2_h [9 * OUT_CH * OUT_CH];
__device__ __nv_bfloat16 g_w_c2_l [9 * OUT_CH * OUT_CH];

// ---------------- PTX helpers ----------------------------------------------------
__device__ __forceinline__ uint32_t smem_u32(const void* p) {
    uint32_t a;
    asm("{ .reg .u64 t; cvta.to.shared.u64 t, %1; cvt.u32.u64 %0, t; }"
        : "=r"(a) : "l"(p));
    return a;
}
__device__ __forceinline__ void ldmx4(uint32_t* r, uint32_t a) {
    asm volatile("ldmatrix.sync.aligned.m8n8.x4.shared.b16 {%0,%1,%2,%3}, [%4];"
        : "=r"(r[0]), "=r"(r[1]), "=r"(r[2]), "=r"(r[3]) : "r"(a));
}
__device__ __forceinline__ void ldmx2(uint32_t* r, uint32_t a) {
    asm volatile("ldmatrix.sync.aligned.m8n8.x2.shared.b16 {%0,%1}, [%2];"
        : "=r"(r[0]), "=r"(r[1]) : "r"(a));
}
__device__ __forceinline__ void mma_bf16(float* d, const uint32_t* A, const uint32_t* B) {
    asm volatile(
        "mma.sync.aligned.m16n8k16.row.col.f32.bf16.bf16.f32 "
        "{%0,%1,%2,%3}, {%4,%5,%6,%7}, {%8,%9}, {%0,%1,%2,%3};"
        : "+f"(d[0]), "+f"(d[1]), "+f"(d[2]), "+f"(d[3])
        : "r"(A[0]), "r"(A[1]), "r"(A[2]), "r"(A[3]), "r"(B[0]), "r"(B[1]));
}
__device__ __forceinline__ void cp_async16(uint32_t dst, const void* src, uint32_t srcsize) {
    asm volatile("cp.async.cg.shared.global [%0], [%1], 16, %2;"
                 :: "r"(dst), "l"(src), "r"(srcsize) : "memory");
}
#define CP_COMMIT() asm volatile("cp.async.commit_group;" ::: "memory")
#define CP_WAIT1()  asm volatile("cp.async.wait_group 1;" ::: "memory")
#define CP_WAIT0()  asm volatile("cp.async.wait_group 0;" ::: "memory")

// ---------------- small kernels ----------------------------------------------------
__global__ void init_stats_kernel() { g_stats[threadIdx.x] = 0.f; }

// (OC,IC,3,3) fp32 -> [tap][oc][ic] bf16 hi/lo
__global__ void pack_weights_kernel(const float* __restrict__ w,
                                    __nv_bfloat16* __restrict__ hi,
                                    __nv_bfloat16* __restrict__ lo,
                                    int OC, int IC) {
    int idx = blockIdx.x * blockDim.x + threadIdx.x;
    int total = 9 * OC * IC;
    if (idx >= total) return;
    int ic  = idx % IC;
    int rem = idx / IC;
    int oc  = rem % OC;
    int tap = rem / OC;
    float v = w[((size_t)oc * IC + ic) * 9 + tap];
    __nv_bfloat16 h = __float2bfloat16(v);
    hi[idx] = h;
    lo[idx] = __float2bfloat16(v - __bfloat162float(h));
}

// ConvTranspose2d(2,2,s=2): thread computes 2x2 output block of one o-channel
__global__ void upcat2_kernel(const float* __restrict__ x1,
                              const float* __restrict__ up_w,
                              const float* __restrict__ up_b) {
    __shared__ float w4[64][4];
    int tid = threadIdx.x;
    int o = blockIdx.y, b = blockIdx.z;
    {
        int i = tid >> 2, k = tid & 3;
        w4[i][k] = up_w[((size_t)i * 64 + o) * 4 + k];
    }
    __syncthreads();
    int pix = blockIdx.x * 256 + tid;
    int ys = pix >> 7, xs = pix & 127;
    float bv = up_b[o];
    float a0 = bv, a1 = bv, a2 = bv, a3 = bv;
    const float* xp = x1 + (size_t)b * C1 * H1 * W1 + pix;
    #pragma unroll 8
    for (int i = 0; i < 64; ++i) {
        float v = __ldg(xp + (size_t)i * (H1 * W1));
        a0 = fmaf(v, w4[i][0], a0);
        a1 = fmaf(v, w4[i][1], a1);
        a2 = fmaf(v, w4[i][2], a2);
        a3 = fmaf(v, w4[i][3], a3);
    }
    float* dst = g_xcat + ((size_t)(b * IN_CH + C1 + o) * H + 2 * ys) * W + 2 * xs;
    *(float2*)dst = make_float2(a0, a1);
    *(float2*)(dst + W) = make_float2(a2, a3);
}

// NCHW fp32 -> NHWC bf16 hi/lo planes (optional BN+ReLU). block (32,8), tile 32c x 32px.
__global__ void nchw_to_planes_kernel(const float* __restrict__ in,
                                      __nv_bfloat16* __restrict__ hi,
                                      __nv_bfloat16* __restrict__ lo,
                                      int C,
                                      const float* __restrict__ sc,
                                      const float* __restrict__ sh) {
    __shared__ float t[32][33];
    int tx = threadIdx.x, ty = threadIdx.y;
    int pix0 = blockIdx.x * 32, cg = blockIdx.y * 32, b = blockIdx.z;
    #pragma unroll
    for (int i = 0; i < 4; ++i) {
        int c = cg + ty + i * 8;
        float v = in[((size_t)b * C + c) * HW + pix0 + tx];
        if (sc) v = fmaxf(fmaf(v, __ldg(sc + c), __ldg(sh + c)), 0.f);
        t[ty + i * 8][tx] = v;
    }
    __syncthreads();
    #pragma unroll
    for (int i = 0; i < 4; ++i) {
        int pxl = ty + i * 8;
        float v = t[tx][pxl];
        __nv_bfloat16 h = __float2bfloat16(v);
        size_t o = ((size_t)b * HW + pix0 + pxl) * C + cg + tx;
        hi[o] = h;
        lo[o] = __float2bfloat16(v - __bfloat162float(h));
    }
}

// deformable gather fused with NHWC bf16 hi/lo transpose. block (32,8).
__global__ void gather_nhwc_kernel() {
    __shared__ float t[32][33];
    int tx = threadIdx.x, ty = threadIdx.y;
    int pix0 = blockIdx.x * 32, cg = blockIdx.y * 32, b = blockIdx.z;
    int pix = pix0 + tx;
    int x = pix & (W - 1), y = pix >> 8;
    const float* ob = g_off + (size_t)b * OFF_CH * HW;
    #pragma unroll
    for (int i = 0; i < 4; ++i) {
        int c = cg + ty + i * 8;
        size_t flat = 2 * ((size_t)c * HW + pix);
        float oy = ob[flat];
        float ox = ob[flat + 1];
        float cy = fminf(fmaxf(oy + (float)y, 0.f), (float)(H - 1));
        float cx = fminf(fmaxf(ox + (float)x, 0.f), (float)(W - 1));
        float y0f = floorf(cy), x0f = floorf(cx);
        int y0 = (int)y0f, y1 = (int)ceilf(cy);
        int xx0 = (int)x0f, xx1 = (int)ceilf(cx);
        const float* xp = g_xcat + ((size_t)b * IN_CH + c) * HW;
        float v00 = xp[y0 * W + xx0];
        float v10 = xp[y1 * W + xx0];
        float v01 = xp[y0 * W + xx1];
        float v11 = xp[y1 * W + xx1];
        float wy = cy - y0f, wx = cx - x0f;
        float vt = fmaf(v10 - v00, wy, v00);
        float vb = fmaf(v11 - v01, wy, v01);
        t[ty + i * 8][tx] = fmaf(vb - vt, wx, vt);
    }
    __syncthreads();
    #pragma unroll
    for (int i = 0; i < 4; ++i) {
        int pxl = ty + i * 8;
        float v = t[tx][pxl];
        __nv_bfloat16 h = __float2bfloat16(v);
        size_t o = ((size_t)b * HW + pix0 + pxl) * IN_CH + cg + tx;
        g_xd_h[o] = h;
        g_xd_l[o] = __float2bfloat16(v - __bfloat162float(h));
    }
}

// ---------------- bf16 split HMMA conv, cp.async pipelined ------------------------
// Block: M=128 px x N=64 oc, 8 warps (4m x 2n). Stage = (tap, icc), K=64.
// Input: pre-converted NHWC bf16 hi/lo planes. MODE 0: plain. MODE 1: +bias,+stats.
template <int IC, int MODE>
__global__ __launch_bounds__(256, 2)
void conv_hmma_kernel(const __nv_bfloat16* __restrict__ xh,
                      const __nv_bfloat16* __restrict__ xl,
                      const __nv_bfloat16* __restrict__ wh,
                      const __nv_bfloat16* __restrict__ wl,
                      int OC,
                      const float* __restrict__ bias, float* __restrict__ out,
                      float* __restrict__ st_sum, float* __restrict__ st_sq) {
    extern __shared__ __align__(128) char smem[];
    constexpr int NSTAGE = (IC / 64) * 9;
    constexpr int A_LO = 18432, B_HI = 36864, B_LO = 46080, SBUF = 55296;

    const int tid = threadIdx.x, lane = tid & 31, wid = tid >> 5;
    const int wm = wid & 3, wn = wid >> 2;
    const int y  = blockIdx.x >> 1;
    const int x0 = (blockIdx.x & 1) * 128;
    const int b  = blockIdx.z;
    const int oc0 = blockIdx.y * 64;
    const uint32_t sb = smem_u32(smem);
    const __nv_bfloat16* xhb = xh + (size_t)b * HW * IC;
    const __nv_bfloat16* xlb = xl + (size_t)b * HW * IC;

    float acc[2][4][4];
    #pragma unroll
    for (int mt = 0; mt < 2; ++mt)
        #pragma unroll
        for (int nt = 0; nt < 4; ++nt)
            #pragma unroll
            for (int q = 0; q < 4; ++q) acc[mt][nt][q] = 0.f;

#define FILL(S, BO) do {                                                            \
    const int _s = (S);                                                             \
    const int _tap = (IC == 128) ? (_s >> 1) : _s;                                  \
    const int _icc = (IC == 128) ? (_s & 1) : 0;                                    \
    const int _dy = _tap / 3 - 1, _dx = _tap % 3 - 1;                               \
    const int _ys = y + _dy;                                                        \
    _Pragma("unroll")                                                               \
    for (int _k = 0; _k < 8; ++_k) {                                                \
        int _c = tid + _k * 256;                                                    \
        int _pl = _c >> 10, _r = _c & 1023;                                         \
        int _px = _r >> 3, _co = _r & 7;                                            \
        int _xs = x0 + _px + _dx;                                                   \
        bool _ok = (_ys >= 0) && (_ys < H) && (_xs >= 0) && (_xs < W);              \
        const __nv_bfloat16* _bs = _pl ? xlb : xhb;                                 \
        size_t _po = _ok ? ((size_t)_ys * W + _xs) * IC : 0;                        \
        cp_async16(sb + (BO) + _pl * A_LO + _px * 144 + _co * 16,                   \
                   (const char*)(_bs + _po) + _icc * 128 + _co * 16,                \
                   _ok ? 16u : 0u);                                                 \
    }                                                                               \
    _Pragma("unroll")                                                               \
    for (int _k = 0; _k < 4; ++_k) {                                                \
        int _c = tid + _k * 256;                                                    \
        int _pl = _c >> 9, _r = _c & 511;                                           \
        int _row = _r >> 3, _co = _r & 7;                                           \
        const __nv_bfloat16* _bs = _pl ? wl : wh;                                   \
        cp_async16(sb + (BO) + B_HI + _pl * (B_LO - B_HI) + _row * 144 + _co * 16,  \
                   (const char*)(_bs + (size_t)(_tap * OC + oc0 + _row) * IC        \
                                 + _icc * 64) + _co * 16, 16u);                     \
    }                                                                               \
} while (0)

#define COMPUTE(BO) do {                                                            \
    _Pragma("unroll")                                                               \
    for (int _ks = 0; _ks < 4; ++_ks) {                                             \
        uint32_t _ah[2][4], _al[2][4], _bh[4][2], _bl[4][2];                        \
        _Pragma("unroll")                                                           \
        for (int _mt = 0; _mt < 2; ++_mt) {                                         \
            uint32_t _a = sb + (BO) + (uint32_t)(wm * 32 + _mt * 16 + (lane & 15))  \
                          * 144 + _ks * 32 + ((lane >> 4) << 4);                    \
            ldmx4(_ah[_mt], _a);                                                    \
            ldmx4(_al[_mt], _a + A_LO);                                             \
        }                                                                           \
        _Pragma("unroll")                                                           \
        for (int _nt = 0; _nt < 4; ++_nt) {                                         \
            uint32_t _ba = sb + (BO) + B_HI                                         \
                          + (uint32_t)(wn * 32 + _nt * 8 + (lane & 7)) * 144        \
                          + _ks * 32 + (((lane >> 3) & 1) << 4);                    \
            ldmx2(_bh[_nt], _ba);                                                   \
            ldmx2(_bl[_nt], _ba + (B_LO - B_HI));                                   \
        }                                                                           \
        _Pragma("unroll")                                                           \
        for (int _mt = 0; _mt < 2; ++_mt)                                           \
            _Pragma("unroll")                                                       \
            for (int _nt = 0; _nt < 4; ++_nt) {                                     \
                mma_bf16(acc[_mt][_nt], _ah[_mt], _bh[_nt]);                        \
                mma_bf16(acc[_mt][_nt], _ah[_mt], _bl[_nt]);                        \
                mma_bf16(acc[_mt][_nt], _al[_mt], _bh[_nt]);                        \
            }                                                                       \
    }                                                                               \
} while (0)

    FILL(0, 0);
    CP_COMMIT();
    for (int s = 0; s < NSTAGE; ++s) {
        if (s + 1 < NSTAGE) {
            FILL(s + 1, ((s + 1) & 1) * SBUF);
            CP_COMMIT();
            CP_WAIT1();
        } else {
            CP_WAIT0();
        }
        __syncthreads();
        COMPUTE((s & 1) * SBUF);
        __syncthreads();
    }

#undef FILL
#undef COMPUTE

    // ---- epilogue
    float* outb = out + ((size_t)b * OC + oc0) * HW + (size_t)y * W + x0;
    const int rr0 = lane >> 2, cj = (lane & 3) * 2;

    if (MODE == 0) {
        #pragma unroll
        for (int mt = 0; mt < 2; ++mt)
            #pragma unroll
            for (int nt = 0; nt < 4; ++nt)
                #pragma unroll
                for (int q = 0; q < 4; ++q) {
                    int p   = wm * 32 + mt * 16 + rr0 + (q >> 1) * 8;
                    int ocl = wn * 32 + nt * 8 + cj + (q & 1);
                    outb[(size_t)ocl * HW + p] = acc[mt][nt][q];
                }
    } else {
        float ss[8], qq[8];
        #pragma unroll
        for (int i = 0; i < 8; ++i) { ss[i] = 0.f; qq[i] = 0.f; }
        #pragma unroll
        for (int nt = 0; nt < 4; ++nt)
            #pragma unroll
            for (int j = 0; j < 2; ++j) {
                int ocl = wn * 32 + nt * 8 + cj + j;
                float bv = __ldg(bias + oc0 + ocl);
                int idx = nt * 2 + j;
                #pragma unroll
                for (int mt = 0; mt < 2; ++mt)
                    #pragma unroll
                    for (int rr = 0; rr < 2; ++rr) {
                        float v = acc[mt][nt][rr * 2 + j] + bv;
                        int p = wm * 32 + mt * 16 + rr0 + rr * 8;
                        outb[(size_t)ocl * HW + p] = v;
                        ss[idx] += v;
                        qq[idx] += v * v;
                    }
            }
        #pragma unroll
        for (int i = 0; i < 8; ++i) {
            #pragma unroll
            for (int o = 4; o <= 16; o <<= 1) {
                ss[i] += __shfl_xor_sync(0xffffffffu, ss[i], o);
                qq[i] += __shfl_xor_sync(0xffffffffu, qq[i], o);
            }
        }
        if (lane < 4) {
            #pragma unroll
            for (int i = 0; i < 8; ++i) {
                int oc = oc0 + wn * 32 + (i >> 1) * 8 + lane * 2 + (i & 1);
                atomicAdd(&st_sum[oc], ss[i]);
                atomicAdd(&st_sq[oc], qq[i]);
            }
        }
    }
}

// ---------------- BN finalize -----------------------------------------------------
__global__ void bnfin_kernel(const float* __restrict__ sum, const float* __restrict__ sq,
                             const float* __restrict__ g, const float* __restrict__ bb,
                             float* __restrict__ scale, float* __restrict__ shift) {
    int c = threadIdx.x;
    float m = sum[c] / BN_N;
    float v = sq[c] / BN_N - m * m;
    float inv = rsqrtf(v + BN_EPS);
    float sc = g[c] * inv;
    scale[c] = sc;
    shift[c] = bb[c] - m * sc;
}

// ---------------- in-place BN + ReLU on output --------------------------------------
__global__ void final_bnrelu_kernel(float* __restrict__ out,
                                    const float* __restrict__ scale,
                                    const float* __restrict__ shift) {
    size_t idx = (size_t)blockIdx.x * blockDim.x + threadIdx.x;
    if (idx >= (size_t)BATCH * OUT_CH * HW) return;
    int c = (int)(idx >> 16) & (OUT_CH - 1);
    out[idx] = fmaxf(fmaf(out[idx], scale[c], shift[c]), 0.f);
}

// ---------------- launch -------------------------------------------------------------
extern "C" void kernel_launch(void* const* d_in, const int* in_sizes, int n_in,
                              void* d_out, int out_size) {
    const float* x1   = (const float*)d_in[0];
    const float* x2   = (const float*)d_in[1];
    const float* up_w = (const float*)d_in[2];
    const float* up_b = (const float*)d_in[3];
    const float* off_w= (const float*)d_in[4];
    const float* c1_w = (const float*)d_in[5];
    const float* c1_b = (const float*)d_in[6];
    const float* g1   = (const float*)d_in[7];
    const float* b1   = (const float*)d_in[8];
    const float* c2_w = (const float*)d_in[9];
    const float* c2_b = (const float*)d_in[10];
    const float* g2   = (const float*)d_in[11];
    const float* b2   = (const float*)d_in[12];
    float* out = (float*)d_out;

    float *xcat, *off, *pre1, *stats, *bn;
    __nv_bfloat16 *xch, *xcl, *xdh, *xdl, *p1h, *p1l;
    __nv_bfloat16 *woh, *wol, *w1h, *w1l, *w2h, *w2l;
    cudaGetSymbolAddress((void**)&xcat,  g_xcat);
    cudaGetSymbolAddress((void**)&off,   g_off);
    cudaGetSymbolAddress((void**)&pre1,  g_pre1);
    cudaGetSymbolAddress((void**)&stats, g_stats);
    cudaGetSymbolAddress((void**)&bn,    g_bn);
    cudaGetSymbolAddress((void**)&xch,   g_xc_h);
    cudaGetSymbolAddress((void**)&xcl,   g_xc_l);
    cudaGetSymbolAddress((void**)&xdh,   g_xd_h);
    cudaGetSymbolAddress((void**)&xdl,   g_xd_l);
    cudaGetSymbolAddress((void**)&p1h,   g_p1_h);
    cudaGetSymbolAddress((void**)&p1l,   g_p1_l);
    cudaGetSymbolAddress((void**)&woh,   g_w_off_h);
    cudaGetSymbolAddress((void**)&wol,   g_w_off_l);
    cudaGetSymbolAddress((void**)&w1h,   g_w_c1_h);
    cudaGetSymbolAddress((void**)&w1l,   g_w_c1_l);
    cudaGetSymbolAddress((void**)&w2h,   g_w_c2_h);
    cudaGetSymbolAddress((void**)&w2l,   g_w_c2_l);

    float* sum1 = stats;            float* sq1 = stats + 64;
    float* sum2 = stats + 128;      float* sq2 = stats + 192;
    float* sc1 = bn;                float* sh1 = bn + 64;
    float* sc2 = bn + 128;          float* sh2 = bn + 192;

    const int SMEM = 2 * 55296;   // 110592
    cudaFuncSetAttribute(conv_hmma_kernel<IN_CH, 0>,
                         cudaFuncAttributeMaxDynamicSharedMemorySize, SMEM);
    cudaFuncSetAttribute(conv_hmma_kernel<IN_CH, 1>,
                         cudaFuncAttributeMaxDynamicSharedMemorySize, SMEM);
    cudaFuncSetAttribute(conv_hmma_kernel<OUT_CH, 1>,
                         cudaFuncAttributeMaxDynamicSharedMemorySize, SMEM);

    // pack weights
    {
        int n0 = 9 * OFF_CH * IN_CH;
        pack_weights_kernel<<<(n0 + 255) / 256, 256>>>(off_w, woh, wol, OFF_CH, IN_CH);
        int n1 = 9 * OUT_CH * IN_CH;
        pack_weights_kernel<<<(n1 + 255) / 256, 256>>>(c1_w, w1h, w1l, OUT_CH, IN_CH);
        int n2 = 9 * OUT_CH * OUT_CH;
        pack_weights_kernel<<<(n2 + 255) / 256, 256>>>(c2_w, w2h, w2l, OUT_CH, OUT_CH);
    }

    init_stats_kernel<<<1, 256>>>();

    // xcat[b][0:64] = x2 (device-to-device copies)
    cudaMemcpyAsync(xcat, x2, (size_t)C1 * HW * sizeof(float),
                    cudaMemcpyDeviceToDevice);
    cudaMemcpyAsync(xcat + (size_t)IN_CH * HW, x2 + (size_t)C1 * HW,
                    (size_t)C1 * HW * sizeof(float), cudaMemcpyDeviceToDevice);

    // xcat[b][64:128] = conv-transpose(x1)
    upcat2_kernel<<<dim3(64, 64, BATCH), 256>>>(x1, up_w, up_b);

    // xcat -> NHWC bf16 planes
    nchw_to_planes_kernel<<<dim3(HW / 32, IN_CH / 32, BATCH), dim3(32, 8)>>>(
        xcat, xch, xcl, IN_CH, nullptr, nullptr);

    // offset conv: (B,128) -> (B,256)
    conv_hmma_kernel<IN_CH, 0><<<dim3(512, OFF_CH / 64, BATCH), 256, SMEM>>>(
        xch, xcl, woh, wol, OFF_CH, nullptr, off, nullptr, nullptr);

    // deformable gather -> NHWC bf16 planes
    gather_nhwc_kernel<<<dim3(HW / 32, IN_CH / 32, BATCH), dim3(32, 8)>>>();

    // conv1: (B,128) -> (B,64), bias + stats
    conv_hmma_kernel<IN_CH, 1><<<dim3(512, 1, BATCH), 256, SMEM>>>(
        xdh, xdl, w1h, w1l, OUT_CH, c1_b, pre1, sum1, sq1);

    bnfin_kernel<<<1, 64>>>(sum1, sq1, g1, b1, sc1, sh1);

    // pre1 -> BN+ReLU -> NHWC bf16 planes
    nchw_to_planes_kernel<<<dim3(HW / 32, OUT_CH / 32, BATCH), dim3(32, 8)>>>(
        pre1, p1h, p1l, OUT_CH, sc1, sh1);

    // conv2: (B,64) -> (B,64), bias + stats
    conv_hmma_kernel<OUT_CH, 1><<<dim3(512, 1, BATCH), 256, SMEM>>>(
        p1h, p1l, w2h, w2l, OUT_CH, c2_b, out, sum2, sq2);

    bnfin_kernel<<<1, 64>>>(sum2, sq2, g2, b2, sc2, sh2);

    {
        size_t n = (size_t)BATCH * OUT_CH * HW;
        final_bnrelu_kernel<<<(unsigned)((n + 255) / 256), 256>>>(out, sc2, sh2);
    }
}

// round 6
// speedup vs baseline: 4.3111x; 1.0107x over previous
#include <cuda_runtime.h>
#include <cuda_bf16.h>
#include <math.h>
#include <stdint.h>

// Problem constants
#define BATCH   2
#define C1      64
#define IN_CH   128
#define OFF_CH  256
#define OUT_CH  64
#define H1      128
#define W1      128
#define H       256
#define W       256
#define HW      (H*W)
#define BN_EPS  1e-5f
#define BN_N    ((float)(BATCH*H*W))

// ---------------- scratch ------------------------------------------------------
__device__ float g_up  [(size_t)BATCH * C1 * HW];       // upsampled half of xcat
__device__ float g_off [(size_t)BATCH * OFF_CH * HW];
__device__ float g_pre1[(size_t)BATCH * OUT_CH * HW];
__device__ float g_stats[4 * OUT_CH];
__device__ float g_bn   [4 * OUT_CH];

// NHWC bf16 hi/lo planes ([b][pix][ic], ic contiguous)
__device__ __nv_bfloat16 g_xc_h[(size_t)BATCH * HW * IN_CH];
__device__ __nv_bfloat16 g_xc_l[(size_t)BATCH * HW * IN_CH];
__device__ __nv_bfloat16 g_xd_h[(size_t)BATCH * HW * IN_CH];
__device__ __nv_bfloat16 g_xd_l[(size_t)BATCH * HW * IN_CH];
__device__ __nv_bfloat16 g_p1_h[(size_t)BATCH * HW * OUT_CH];
__device__ __nv_bfloat16 g_p1_l[(size_t)BATCH * HW * OUT_CH];

// packed weights [tap][oc][ic] bf16 hi/lo
__device__ __nv_bfloat16 g_w_off_h[9 * OFF_CH * IN_CH];
__device__ __nv_bfloat16 g_w_off_l[9 * OFF_CH * IN_CH];
__device__ __nv_bfloat16 g_w_c1_h [9 * OUT_CH * IN_CH];
__device__ __nv_bfloat16 g_w_c1_l [9 * OUT_CH * IN_CH];
__device__ __nv_bfloat16 g_w_c2_h [9 * OUT_CH * OUT_CH];
__device__ __nv_bfloat16 g_w_c2_l [9 * OUT_CH * OUT_CH];

// ---------------- PTX helpers ----------------------------------------------------
__device__ __forceinline__ uint32_t smem_u32(const void* p) {
    uint32_t a;
    asm("{ .reg .u64 t; cvta.to.shared.u64 t, %1; cvt.u32.u64 %0, t; }"
        : "=r"(a) : "l"(p));
    return a;
}
__device__ __forceinline__ void ldmx4(uint32_t* r, uint32_t a) {
    asm volatile("ldmatrix.sync.aligned.m8n8.x4.shared.b16 {%0,%1,%2,%3}, [%4];"
        : "=r"(r[0]), "=r"(r[1]), "=r"(r[2]), "=r"(r[3]) : "r"(a));
}
__device__ __forceinline__ void ldmx2(uint32_t* r, uint32_t a) {
    asm volatile("ldmatrix.sync.aligned.m8n8.x2.shared.b16 {%0,%1}, [%2];"
        : "=r"(r[0]), "=r"(r[1]) : "r"(a));
}
__device__ __forceinline__ void mma_bf16(float* d, const uint32_t* A, const uint32_t* B) {
    asm volatile(
        "mma.sync.aligned.m16n8k16.row.col.f32.bf16.bf16.f32 "
        "{%0,%1,%2,%3}, {%4,%5,%6,%7}, {%8,%9}, {%0,%1,%2,%3};"
        : "+f"(d[0]), "+f"(d[1]), "+f"(d[2]), "+f"(d[3])
        : "r"(A[0]), "r"(A[1]), "r"(A[2]), "r"(A[3]), "r"(B[0]), "r"(B[1]));
}
__device__ __forceinline__ void cp_async16(uint32_t dst, const void* src, uint32_t srcsize) {
    asm volatile("cp.async.cg.shared.global [%0], [%1], 16, %2;"
                 :: "r"(dst), "l"(src), "r"(srcsize) : "memory");
}
#define CP_COMMIT() asm volatile("cp.async.commit_group;" ::: "memory")
#define CP_WAIT1()  asm volatile("cp.async.wait_group 1;" ::: "memory")
#define CP_WAIT0()  asm volatile("cp.async.wait_group 0;" ::: "memory")

// ---------------- small kernels ----------------------------------------------------
__global__ void init_stats_kernel() { g_stats[threadIdx.x] = 0.f; }

// (OC,IC,3,3) fp32 -> [tap][oc][ic] bf16 hi/lo
__global__ void pack_weights_kernel(const float* __restrict__ w,
                                    __nv_bfloat16* __restrict__ hi,
                                    __nv_bfloat16* __restrict__ lo,
                                    int OC, int IC) {
    int idx = blockIdx.x * blockDim.x + threadIdx.x;
    int total = 9 * OC * IC;
    if (idx >= total) return;
    int ic  = idx % IC;
    int rem = idx / IC;
    int oc  = rem % OC;
    int tap = rem / OC;
    float v = w[((size_t)oc * IC + ic) * 9 + tap];
    __nv_bfloat16 h = __float2bfloat16(v);
    hi[idx] = h;
    lo[idx] = __float2bfloat16(v - __bfloat162float(h));
}

// ConvTranspose2d(2,2,s=2): thread computes 2x2 output block of one o-channel
__global__ void upcat2_kernel(const float* __restrict__ x1,
                              const float* __restrict__ up_w,
                              const float* __restrict__ up_b) {
    __shared__ float w4[64][4];
    int tid = threadIdx.x;
    int o = blockIdx.y, b = blockIdx.z;
    {
        int i = tid >> 2, k = tid & 3;
        w4[i][k] = up_w[((size_t)i * 64 + o) * 4 + k];
    }
    __syncthreads();
    int pix = blockIdx.x * 256 + tid;
    int ys = pix >> 7, xs = pix & 127;
    float bv = up_b[o];
    float a0 = bv, a1 = bv, a2 = bv, a3 = bv;
    const float* xp = x1 + (size_t)b * C1 * H1 * W1 + pix;
    #pragma unroll 8
    for (int i = 0; i < 64; ++i) {
        float v = __ldg(xp + (size_t)i * (H1 * W1));
        a0 = fmaf(v, w4[i][0], a0);
        a1 = fmaf(v, w4[i][1], a1);
        a2 = fmaf(v, w4[i][2], a2);
        a3 = fmaf(v, w4[i][3], a3);
    }
    float* dst = g_up + ((size_t)(b * C1 + o) * H + 2 * ys) * W + 2 * xs;
    *(float2*)dst = make_float2(a0, a1);
    *(float2*)(dst + W) = make_float2(a2, a3);
}

// NCHW fp32 (two sources, split at channel S) -> NHWC bf16 hi/lo (optional BN+ReLU)
__global__ void nchw_to_planes_kernel(const float* __restrict__ src_lo,
                                      const float* __restrict__ src_hi,
                                      __nv_bfloat16* __restrict__ hi,
                                      __nv_bfloat16* __restrict__ lo,
                                      int C, int S,
                                      const float* __restrict__ sc,
                                      const float* __restrict__ sh) {
    __shared__ float t[32][33];
    int tx = threadIdx.x, ty = threadIdx.y;
    int pix0 = blockIdx.x * 32, cg = blockIdx.y * 32, b = blockIdx.z;
    #pragma unroll
    for (int i = 0; i < 4; ++i) {
        int c = cg + ty + i * 8;
        const float* sp = (c < S) ? src_lo + ((size_t)b * S + c) * HW
                                  : src_hi + ((size_t)b * (C - S) + c - S) * HW;
        float v = sp[pix0 + tx];
        if (sc) v = fmaxf(fmaf(v, __ldg(sc + c), __ldg(sh + c)), 0.f);
        t[ty + i * 8][tx] = v;
    }
    __syncthreads();
    #pragma unroll
    for (int i = 0; i < 4; ++i) {
        int pxl = ty + i * 8;
        float v = t[tx][pxl];
        __nv_bfloat16 h = __float2bfloat16(v);
        size_t o = ((size_t)b * HW + pix0 + pxl) * C + cg + tx;
        hi[o] = h;
        lo[o] = __float2bfloat16(v - __bfloat162float(h));
    }
}

// deformable gather fused with NHWC bf16 hi/lo transpose. block (32,8).
__global__ void gather_nhwc_kernel(const float* __restrict__ x2) {
    __shared__ float t[32][33];
    int tx = threadIdx.x, ty = threadIdx.y;
    int pix0 = blockIdx.x * 32, cg = blockIdx.y * 32, b = blockIdx.z;
    int pix = pix0 + tx;
    int x = pix & (W - 1), y = pix >> 8;
    const float* ob = g_off + (size_t)b * OFF_CH * HW;
    #pragma unroll
    for (int i = 0; i < 4; ++i) {
        int c = cg + ty + i * 8;
        size_t flat = 2 * ((size_t)c * HW + pix);
        float oy = ob[flat];
        float ox = ob[flat + 1];
        float cy = fminf(fmaxf(oy + (float)y, 0.f), (float)(H - 1));
        float cx = fminf(fmaxf(ox + (float)x, 0.f), (float)(W - 1));
        float y0f = floorf(cy), x0f = floorf(cx);
        int y0 = (int)y0f, y1 = (int)ceilf(cy);
        int xx0 = (int)x0f, xx1 = (int)ceilf(cx);
        const float* xp = (c < C1) ? x2 + ((size_t)b * C1 + c) * HW
                                   : g_up + ((size_t)b * C1 + c - C1) * HW;
        float v00 = xp[y0 * W + xx0];
        float v10 = xp[y1 * W + xx0];
        float v01 = xp[y0 * W + xx1];
        float v11 = xp[y1 * W + xx1];
        float wy = cy - y0f, wx = cx - x0f;
        float vt = fmaf(v10 - v00, wy, v00);
        float vb = fmaf(v11 - v01, wy, v01);
        t[ty + i * 8][tx] = fmaf(vb - vt, wx, vt);
    }
    __syncthreads();
    #pragma unroll
    for (int i = 0; i < 4; ++i) {
        int pxl = ty + i * 8;
        float v = t[tx][pxl];
        __nv_bfloat16 h = __float2bfloat16(v);
        size_t o = ((size_t)b * HW + pix0 + pxl) * IN_CH + cg + tx;
        g_xd_h[o] = h;
        g_xd_l[o] = __float2bfloat16(v - __bfloat162float(h));
    }
}

// ---------------- bf16 split HMMA conv, cp.async pipelined ------------------------
// Block: M=128 px x N=64 oc, 4 warps (2m x 2n), warp tile 64x32 (4 m-frags, 4 n-frags).
// Stage = (tap, icc), K=64. MODE 0: plain. MODE 1: +bias,+stats.
template <int IC, int MODE>
__global__ __launch_bounds__(128, 2)
void conv_hmma_kernel(const __nv_bfloat16* __restrict__ xh,
                      const __nv_bfloat16* __restrict__ xl,
                      const __nv_bfloat16* __restrict__ wh,
                      const __nv_bfloat16* __restrict__ wl,
                      int OC,
                      const float* __restrict__ bias, float* __restrict__ out,
                      float* __restrict__ st_sum, float* __restrict__ st_sq) {
    extern __shared__ __align__(128) char smem[];
    constexpr int NSTAGE = (IC / 64) * 9;
    constexpr int A_LO = 18432, B_HI = 36864, B_LO = 46080, SBUF = 55296;

    const int tid = threadIdx.x, lane = tid & 31, wid = tid >> 5;
    const int wm = wid & 1, wn = wid >> 1;
    const int y  = blockIdx.x >> 1;
    const int x0 = (blockIdx.x & 1) * 128;
    const int b  = blockIdx.z;
    const int oc0 = blockIdx.y * 64;
    const uint32_t sb = smem_u32(smem);
    const __nv_bfloat16* xhb = xh + (size_t)b * HW * IC;
    const __nv_bfloat16* xlb = xl + (size_t)b * HW * IC;

    float acc[4][4][4];
    #pragma unroll
    for (int mf = 0; mf < 4; ++mf)
        #pragma unroll
        for (int nf = 0; nf < 4; ++nf)
            #pragma unroll
            for (int q = 0; q < 4; ++q) acc[mf][nf][q] = 0.f;

#define FILL(S, BO) do {                                                            \
    const int _s = (S);                                                             \
    const int _tap = (IC == 128) ? (_s >> 1) : _s;                                  \
    const int _icc = (IC == 128) ? (_s & 1) : 0;                                    \
    const int _dy = _tap / 3 - 1, _dx = _tap % 3 - 1;                               \
    const int _ys = y + _dy;                                                        \
    _Pragma("unroll")                                                               \
    for (int _k = 0; _k < 16; ++_k) {                                               \
        int _c = tid + _k * 128;                                                    \
        int _pl = _c >> 10, _r = _c & 1023;                                         \
        int _px = _r >> 3, _co = _r & 7;                                            \
        int _xs = x0 + _px + _dx;                                                   \
        bool _ok = (_ys >= 0) && (_ys < H) && (_xs >= 0) && (_xs < W);              \
        const __nv_bfloat16* _bs = _pl ? xlb : xhb;                                 \
        size_t _po = _ok ? ((size_t)_ys * W + _xs) * IC : 0;                        \
        cp_async16(sb + (BO) + _pl * A_LO + _px * 144 + _co * 16,                   \
                   (const char*)(_bs + _po) + _icc * 128 + _co * 16,                \
                   _ok ? 16u : 0u);                                                 \
    }                                                                               \
    _Pragma("unroll")                                                               \
    for (int _k = 0; _k < 8; ++_k) {                                                \
        int _c = tid + _k * 128;                                                    \
        int _pl = _c >> 9, _r = _c & 511;                                           \
        int _row = _r >> 3, _co = _r & 7;                                           \
        const __nv_bfloat16* _bs = _pl ? wl : wh;                                   \
        cp_async16(sb + (BO) + B_HI + _pl * (B_LO - B_HI) + _row * 144 + _co * 16,  \
                   (const char*)(_bs + (size_t)(_tap * OC + oc0 + _row) * IC        \
                                 + _icc * 64) + _co * 16, 16u);                     \
    }                                                                               \
} while (0)

#define COMPUTE(BO) do {                                                            \
    _Pragma("unroll")                                                               \
    for (int _ks = 0; _ks < 4; ++_ks) {                                             \
        uint32_t _ah[4][4], _al[4][4], _bh[4][2], _bl[4][2];                        \
        _Pragma("unroll")                                                           \
        for (int _mf = 0; _mf < 4; ++_mf) {                                         \
            uint32_t _a = sb + (BO) + (uint32_t)(wm * 64 + _mf * 16 + (lane & 15))  \
                          * 144 + _ks * 32 + ((lane >> 4) << 4);                    \
            ldmx4(_ah[_mf], _a);                                                    \
            ldmx4(_al[_mf], _a + A_LO);                                             \
        }                                                                           \
        _Pragma("unroll")                                                           \
        for (int _nf = 0; _nf < 4; ++_nf) {                                         \
            uint32_t _ba = sb + (BO) + B_HI                                         \
                          + (uint32_t)(wn * 32 + _nf * 8 + (lane & 7)) * 144        \
                          + _ks * 32 + (((lane >> 3) & 1) << 4);                    \
            ldmx2(_bh[_nf], _ba);                                                   \
            ldmx2(_bl[_nf], _ba + (B_LO - B_HI));                                   \
        }                                                                           \
        _Pragma("unroll")                                                           \
        for (int _mf = 0; _mf < 4; ++_mf)                                           \
            _Pragma("unroll")                                                       \
            for (int _nf = 0; _nf < 4; ++_nf) {                                     \
                mma_bf16(acc[_mf][_nf], _ah[_mf], _bh[_nf]);                        \
                mma_bf16(acc[_mf][_nf], _ah[_mf], _bl[_nf]);                        \
                mma_bf16(acc[_mf][_nf], _al[_mf], _bh[_nf]);                        \
            }                                                                       \
    }                                                                               \
} while (0)

    FILL(0, 0);
    CP_COMMIT();
    for (int s = 0; s < NSTAGE; ++s) {
        if (s + 1 < NSTAGE) {
            FILL(s + 1, ((s + 1) & 1) * SBUF);
            CP_COMMIT();
            CP_WAIT1();
        } else {
            CP_WAIT0();
        }
        __syncthreads();
        COMPUTE((s & 1) * SBUF);
        __syncthreads();
    }

#undef FILL
#undef COMPUTE

    // ---- epilogue
    float* outb = out + ((size_t)b * OC + oc0) * HW + (size_t)y * W + x0;
    const int rr0 = lane >> 2, cj = (lane & 3) * 2;

    if (MODE == 0) {
        #pragma unroll
        for (int mf = 0; mf < 4; ++mf)
            #pragma unroll
            for (int nf = 0; nf < 4; ++nf)
                #pragma unroll
                for (int q = 0; q < 4; ++q) {
                    int p   = wm * 64 + mf * 16 + rr0 + (q >> 1) * 8;
                    int ocl = wn * 32 + nf * 8 + cj + (q & 1);
                    outb[(size_t)ocl * HW + p] = acc[mf][nf][q];
                }
    } else {
        float ss[8], qq[8];
        #pragma unroll
        for (int i = 0; i < 8; ++i) { ss[i] = 0.f; qq[i] = 0.f; }
        #pragma unroll
        for (int nf = 0; nf < 4; ++nf)
            #pragma unroll
            for (int j = 0; j < 2; ++j) {
                int ocl = wn * 32 + nf * 8 + cj + j;
                float bv = __ldg(bias + oc0 + ocl);
                int idx = nf * 2 + j;
                #pragma unroll
                for (int mf = 0; mf < 4; ++mf)
                    #pragma unroll
                    for (int rr = 0; rr < 2; ++rr) {
                        float v = acc[mf][nf][rr * 2 + j] + bv;
                        int p = wm * 64 + mf * 16 + rr0 + rr * 8;
                        outb[(size_t)ocl * HW + p] = v;
                        ss[idx] += v;
                        qq[idx] += v * v;
                    }
            }
        #pragma unroll
        for (int i = 0; i < 8; ++i) {
            #pragma unroll
            for (int o = 4; o <= 16; o <<= 1) {
                ss[i] += __shfl_xor_sync(0xffffffffu, ss[i], o);
                qq[i] += __shfl_xor_sync(0xffffffffu, qq[i], o);
            }
        }
        if (lane < 4) {
            #pragma unroll
            for (int i = 0; i < 8; ++i) {
                int oc = oc0 + wn * 32 + (i >> 1) * 8 + lane * 2 + (i & 1);
                atomicAdd(&st_sum[oc], ss[i]);
                atomicAdd(&st_sq[oc], qq[i]);
            }
        }
    }
}

// ---------------- BN finalize -----------------------------------------------------
__global__ void bnfin_kernel(const float* __restrict__ sum, const float* __restrict__ sq,
                             const float* __restrict__ g, const float* __restrict__ bb,
                             float* __restrict__ scale, float* __restrict__ shift) {
    int c = threadIdx.x;
    float m = sum[c] / BN_N;
    float v = sq[c] / BN_N - m * m;
    float inv = rsqrtf(v + BN_EPS);
    float sc = g[c] * inv;
    scale[c] = sc;
    shift[c] = bb[c] - m * sc;
}

// ---------------- in-place BN + ReLU on output --------------------------------------
__global__ void final_bnrelu_kernel(float* __restrict__ out,
                                    const float* __restrict__ scale,
                                    const float* __restrict__ shift) {
    size_t idx = (size_t)blockIdx.x * blockDim.x + threadIdx.x;
    if (idx >= (size_t)BATCH * OUT_CH * HW) return;
    int c = (int)(idx >> 16) & (OUT_CH - 1);
    out[idx] = fmaxf(fmaf(out[idx], scale[c], shift[c]), 0.f);
}

// ---------------- launch -------------------------------------------------------------
extern "C" void kernel_launch(void* const* d_in, const int* in_sizes, int n_in,
                              void* d_out, int out_size) {
    const float* x1   = (const float*)d_in[0];
    const float* x2   = (const float*)d_in[1];
    const float* up_w = (const float*)d_in[2];
    const float* up_b = (const float*)d_in[3];
    const float* off_w= (const float*)d_in[4];
    const float* c1_w = (const float*)d_in[5];
    const float* c1_b = (const float*)d_in[6];
    const float* g1   = (const float*)d_in[7];
    const float* b1   = (const float*)d_in[8];
    const float* c2_w = (const float*)d_in[9];
    const float* c2_b = (const float*)d_in[10];
    const float* g2   = (const float*)d_in[11];
    const float* b2   = (const float*)d_in[12];
    float* out = (float*)d_out;

    float *up, *off, *pre1, *stats, *bn;
    __nv_bfloat16 *xch, *xcl, *xdh, *xdl, *p1h, *p1l;
    __nv_bfloat16 *woh, *wol, *w1h, *w1l, *w2h, *w2l;
    cudaGetSymbolAddress((void**)&up,    g_up);
    cudaGetSymbolAddress((void**)&off,   g_off);
    cudaGetSymbolAddress((void**)&pre1,  g_pre1);
    cudaGetSymbolAddress((void**)&stats, g_stats);
    cudaGetSymbolAddress((void**)&bn,    g_bn);
    cudaGetSymbolAddress((void**)&xch,   g_xc_h);
    cudaGetSymbolAddress((void**)&xcl,   g_xc_l);
    cudaGetSymbolAddress((void**)&xdh,   g_xd_h);
    cudaGetSymbolAddress((void**)&xdl,   g_xd_l);
    cudaGetSymbolAddress((void**)&p1h,   g_p1_h);
    cudaGetSymbolAddress((void**)&p1l,   g_p1_l);
    cudaGetSymbolAddress((void**)&woh,   g_w_off_h);
    cudaGetSymbolAddress((void**)&wol,   g_w_off_l);
    cudaGetSymbolAddress((void**)&w1h,   g_w_c1_h);
    cudaGetSymbolAddress((void**)&w1l,   g_w_c1_l);
    cudaGetSymbolAddress((void**)&w2h,   g_w_c2_h);
    cudaGetSymbolAddress((void**)&w2l,   g_w_c2_l);

    float* sum1 = stats;            float* sq1 = stats + 64;
    float* sum2 = stats + 128;      float* sq2 = stats + 192;
    float* sc1 = bn;                float* sh1 = bn + 64;
    float* sc2 = bn + 128;          float* sh2 = bn + 192;

    const int SMEM = 2 * 55296;   // 110592
    cudaFuncSetAttribute(conv_hmma_kernel<IN_CH, 0>,
                         cudaFuncAttributeMaxDynamicSharedMemorySize, SMEM);
    cudaFuncSetAttribute(conv_hmma_kernel<IN_CH, 1>,
                         cudaFuncAttributeMaxDynamicSharedMemorySize, SMEM);
    cudaFuncSetAttribute(conv_hmma_kernel<OUT_CH, 1>,
                         cudaFuncAttributeMaxDynamicSharedMemorySize, SMEM);

    // 1. pack offset weights
    {
        int n0 = 9 * OFF_CH * IN_CH;
        pack_weights_kernel<<<(n0 + 255) / 256, 256>>>(off_w, woh, wol, OFF_CH, IN_CH);
    }
    // 2. conv-transpose upsample
    upcat2_kernel<<<dim3(64, 64, BATCH), 256>>>(x1, up_w, up_b);
    // 3. concat (x2 | up) -> NHWC bf16 planes
    nchw_to_planes_kernel<<<dim3(HW / 32, IN_CH / 32, BATCH), dim3(32, 8)>>>(
        x2, up, xch, xcl, IN_CH, C1, nullptr, nullptr);
    // 4. offset conv (profiled launch): (B,128) -> (B,256)
    conv_hmma_kernel<IN_CH, 0><<<dim3(512, OFF_CH / 64, BATCH), 128, SMEM>>>(
        xch, xcl, woh, wol, OFF_CH, nullptr, off, nullptr, nullptr);
    // 5-7. remaining packs + stats init
    {
        int n1 = 9 * OUT_CH * IN_CH;
        pack_weights_kernel<<<(n1 + 255) / 256, 256>>>(c1_w, w1h, w1l, OUT_CH, IN_CH);
        int n2 = 9 * OUT_CH * OUT_CH;
        pack_weights_kernel<<<(n2 + 255) / 256, 256>>>(c2_w, w2h, w2l, OUT_CH, OUT_CH);
    }
    init_stats_kernel<<<1, 256>>>();
    // 8. deformable gather -> NHWC bf16 planes
    gather_nhwc_kernel<<<dim3(HW / 32, IN_CH / 32, BATCH), dim3(32, 8)>>>(x2);
    // 9. conv1: (B,128) -> (B,64), bias + stats
    conv_hmma_kernel<IN_CH, 1><<<dim3(512, 1, BATCH), 128, SMEM>>>(
        xdh, xdl, w1h, w1l, OUT_CH, c1_b, pre1, sum1, sq1);
    bnfin_kernel<<<1, 64>>>(sum1, sq1, g1, b1, sc1, sh1);
    // 10. pre1 -> BN+ReLU -> NHWC bf16 planes
    nchw_to_planes_kernel<<<dim3(HW / 32, OUT_CH / 32, BATCH), dim3(32, 8)>>>(
        pre1, pre1, p1h, p1l, OUT_CH, OUT_CH, sc1, sh1);
    // 11. conv2: (B,64) -> (B,64), bias + stats
    conv_hmma_kernel<OUT_CH, 1><<<dim3(512, 1, BATCH), 128, SMEM>>>(
        p1h, p1l, w2h, w2l, OUT_CH, c2_b, out, sum2, sq2);
    bnfin_kernel<<<1, 64>>>(sum2, sq2, g2, b2, sc2, sh2);
    // 12. final BN + ReLU
    {
        size_t n = (size_t)BATCH * OUT_CH * HW;
        final_bnrelu_kernel<<<(unsigned)((n + 255) / 256), 256>>>(out, sc2, sh2);
    }
}

// round 7
// speedup vs baseline: 4.3170x; 1.0014x over previous
#include <cuda_runtime.h>
#include <cuda_bf16.h>
#include <math.h>
#include <stdint.h>

// Problem constants
#define BATCH   2
#define C1      64
#define IN_CH   128
#define OFF_CH  256
#define OUT_CH  64
#define H1      128
#define W1      128
#define H       256
#define W       256
#define HW      (H*W)
#define BN_EPS  1e-5f
#define BN_N    ((float)(BATCH*H*W))

// ---------------- scratch ------------------------------------------------------
__device__ float g_up  [(size_t)BATCH * C1 * HW];       // upsampled half of xcat
__device__ float g_off [(size_t)BATCH * OFF_CH * HW];
__device__ float g_pre1[(size_t)BATCH * OUT_CH * HW];
__device__ float g_stats[4 * OUT_CH];
__device__ float g_bn   [4 * OUT_CH];

// NHWC bf16 hi/lo planes ([b][pix][ic], ic contiguous)
__device__ __nv_bfloat16 g_xc_h[(size_t)BATCH * HW * IN_CH];
__device__ __nv_bfloat16 g_xc_l[(size_t)BATCH * HW * IN_CH];
__device__ __nv_bfloat16 g_xd_h[(size_t)BATCH * HW * IN_CH];
__device__ __nv_bfloat16 g_xd_l[(size_t)BATCH * HW * IN_CH];
__device__ __nv_bfloat16 g_p1_h[(size_t)BATCH * HW * OUT_CH];
__device__ __nv_bfloat16 g_p1_l[(size_t)BATCH * HW * OUT_CH];

// packed weights [tap][oc][ic] bf16 hi/lo
__device__ __nv_bfloat16 g_w_off_h[9 * OFF_CH * IN_CH];
__device__ __nv_bfloat16 g_w_off_l[9 * OFF_CH * IN_CH];
__device__ __nv_bfloat16 g_w_c1_h [9 * OUT_CH * IN_CH];
__device__ __nv_bfloat16 g_w_c1_l [9 * OUT_CH * IN_CH];
__device__ __nv_bfloat16 g_w_c2_h [9 * OUT_CH * OUT_CH];
__device__ __nv_bfloat16 g_w_c2_l [9 * OUT_CH * OUT_CH];

// ---------------- PTX helpers ----------------------------------------------------
__device__ __forceinline__ uint32_t smem_u32(const void* p) {
    uint32_t a;
    asm("{ .reg .u64 t; cvta.to.shared.u64 t, %1; cvt.u32.u64 %0, t; }"
        : "=r"(a) : "l"(p));
    return a;
}
__device__ __forceinline__ void ldmx4(uint32_t* r, uint32_t a) {
    asm volatile("ldmatrix.sync.aligned.m8n8.x4.shared.b16 {%0,%1,%2,%3}, [%4];"
        : "=r"(r[0]), "=r"(r[1]), "=r"(r[2]), "=r"(r[3]) : "r"(a));
}
__device__ __forceinline__ void ldmx2(uint32_t* r, uint32_t a) {
    asm volatile("ldmatrix.sync.aligned.m8n8.x2.shared.b16 {%0,%1}, [%2];"
        : "=r"(r[0]), "=r"(r[1]) : "r"(a));
}
__device__ __forceinline__ void mma_bf16(float* d, const uint32_t* A, const uint32_t* B) {
    asm volatile(
        "mma.sync.aligned.m16n8k16.row.col.f32.bf16.bf16.f32 "
        "{%0,%1,%2,%3}, {%4,%5,%6,%7}, {%8,%9}, {%0,%1,%2,%3};"
        : "+f"(d[0]), "+f"(d[1]), "+f"(d[2]), "+f"(d[3])
        : "r"(A[0]), "r"(A[1]), "r"(A[2]), "r"(A[3]), "r"(B[0]), "r"(B[1]));
}
__device__ __forceinline__ void cp_async16(uint32_t dst, const void* src, uint32_t srcsize) {
    asm volatile("cp.async.cg.shared.global [%0], [%1], 16, %2;"
                 :: "r"(dst), "l"(src), "r"(srcsize) : "memory");
}
#define CP_COMMIT() asm volatile("cp.async.commit_group;" ::: "memory")
#define CP_WAIT1()  asm volatile("cp.async.wait_group 1;" ::: "memory")
#define CP_WAIT0()  asm volatile("cp.async.wait_group 0;" ::: "memory")

// ---------------- small kernels ----------------------------------------------------
__global__ void init_stats_kernel() { g_stats[threadIdx.x] = 0.f; }

// (OC,IC,3,3) fp32 -> [tap][oc][ic] bf16 hi/lo
__global__ void pack_weights_kernel(const float* __restrict__ w,
                                    __nv_bfloat16* __restrict__ hi,
                                    __nv_bfloat16* __restrict__ lo,
                                    int OC, int IC) {
    int idx = blockIdx.x * blockDim.x + threadIdx.x;
    int total = 9 * OC * IC;
    if (idx >= total) return;
    int ic  = idx % IC;
    int rem = idx / IC;
    int oc  = rem % OC;
    int tap = rem / OC;
    float v = w[((size_t)oc * IC + ic) * 9 + tap];
    __nv_bfloat16 h = __float2bfloat16(v);
    hi[idx] = h;
    lo[idx] = __float2bfloat16(v - __bfloat162float(h));
}

// ConvTranspose2d(2,2,s=2): thread computes 2x2 output block of one o-channel
__global__ void upcat2_kernel(const float* __restrict__ x1,
                              const float* __restrict__ up_w,
                              const float* __restrict__ up_b) {
    __shared__ float w4[64][4];
    int tid = threadIdx.x;
    int o = blockIdx.y, b = blockIdx.z;
    {
        int i = tid >> 2, k = tid & 3;
        w4[i][k] = up_w[((size_t)i * 64 + o) * 4 + k];
    }
    __syncthreads();
    int pix = blockIdx.x * 256 + tid;
    int ys = pix >> 7, xs = pix & 127;
    float bv = up_b[o];
    float a0 = bv, a1 = bv, a2 = bv, a3 = bv;
    const float* xp = x1 + (size_t)b * C1 * H1 * W1 + pix;
    #pragma unroll 8
    for (int i = 0; i < 64; ++i) {
        float v = __ldg(xp + (size_t)i * (H1 * W1));
        a0 = fmaf(v, w4[i][0], a0);
        a1 = fmaf(v, w4[i][1], a1);
        a2 = fmaf(v, w4[i][2], a2);
        a3 = fmaf(v, w4[i][3], a3);
    }
    float* dst = g_up + ((size_t)(b * C1 + o) * H + 2 * ys) * W + 2 * xs;
    *(float2*)dst = make_float2(a0, a1);
    *(float2*)(dst + W) = make_float2(a2, a3);
}

// NCHW fp32 (two sources, split at channel S) -> NHWC bf16 hi/lo (optional BN+ReLU)
__global__ void nchw_to_planes_kernel(const float* __restrict__ src_lo,
                                      const float* __restrict__ src_hi,
                                      __nv_bfloat16* __restrict__ hi,
                                      __nv_bfloat16* __restrict__ lo,
                                      int C, int S,
                                      const float* __restrict__ sc,
                                      const float* __restrict__ sh) {
    __shared__ float t[32][33];
    int tx = threadIdx.x, ty = threadIdx.y;
    int pix0 = blockIdx.x * 32, cg = blockIdx.y * 32, b = blockIdx.z;
    #pragma unroll
    for (int i = 0; i < 4; ++i) {
        int c = cg + ty + i * 8;
        const float* sp = (c < S) ? src_lo + ((size_t)b * S + c) * HW
                                  : src_hi + ((size_t)b * (C - S) + c - S) * HW;
        float v = sp[pix0 + tx];
        if (sc) v = fmaxf(fmaf(v, __ldg(sc + c), __ldg(sh + c)), 0.f);
        t[ty + i * 8][tx] = v;
    }
    __syncthreads();
    #pragma unroll
    for (int i = 0; i < 4; ++i) {
        int pxl = ty + i * 8;
        float v = t[tx][pxl];
        __nv_bfloat16 h = __float2bfloat16(v);
        size_t o = ((size_t)b * HW + pix0 + pxl) * C + cg + tx;
        hi[o] = h;
        lo[o] = __float2bfloat16(v - __bfloat162float(h));
    }
}

// deformable gather fused with NHWC bf16 hi/lo transpose. block (32,8).
__global__ void gather_nhwc_kernel(const float* __restrict__ x2) {
    __shared__ float t[32][33];
    int tx = threadIdx.x, ty = threadIdx.y;
    int pix0 = blockIdx.x * 32, cg = blockIdx.y * 32, b = blockIdx.z;
    int pix = pix0 + tx;
    int x = pix & (W - 1), y = pix >> 8;
    const float* ob = g_off + (size_t)b * OFF_CH * HW;
    #pragma unroll
    for (int i = 0; i < 4; ++i) {
        int c = cg + ty + i * 8;
        size_t flat = 2 * ((size_t)c * HW + pix);
        float oy = ob[flat];
        float ox = ob[flat + 1];
        float cy = fminf(fmaxf(oy + (float)y, 0.f), (float)(H - 1));
        float cx = fminf(fmaxf(ox + (float)x, 0.f), (float)(W - 1));
        float y0f = floorf(cy), x0f = floorf(cx);
        int y0 = (int)y0f, y1 = (int)ceilf(cy);
        int xx0 = (int)x0f, xx1 = (int)ceilf(cx);
        const float* xp = (c < C1) ? x2 + ((size_t)b * C1 + c) * HW
                                   : g_up + ((size_t)b * C1 + c - C1) * HW;
        float v00 = xp[y0 * W + xx0];
        float v10 = xp[y1 * W + xx0];
        float v01 = xp[y0 * W + xx1];
        float v11 = xp[y1 * W + xx1];
        float wy = cy - y0f, wx = cx - x0f;
        float vt = fmaf(v10 - v00, wy, v00);
        float vb = fmaf(v11 - v01, wy, v01);
        t[ty + i * 8][tx] = fmaf(vb - vt, wx, vt);
    }
    __syncthreads();
    #pragma unroll
    for (int i = 0; i < 4; ++i) {
        int pxl = ty + i * 8;
        float v = t[tx][pxl];
        __nv_bfloat16 h = __float2bfloat16(v);
        size_t o = ((size_t)b * HW + pix0 + pxl) * IN_CH + cg + tx;
        g_xd_h[o] = h;
        g_xd_l[o] = __float2bfloat16(v - __bfloat162float(h));
    }
}

// ---------------- bf16 split HMMA conv, cp.async pipelined ------------------------
// Block: M=128 px x N=64 oc, 4 warps (2m x 2n), warp tile 64x32 (4 m-frags, 4 n-frags).
// Stage = (tap, icc), K=64. MODE 0: plain. MODE 1: +bias,+stats.
template <int IC, int MODE>
__global__ __launch_bounds__(128, 2)
void conv_hmma_kernel(const __nv_bfloat16* __restrict__ xh,
                      const __nv_bfloat16* __restrict__ xl,
                      const __nv_bfloat16* __restrict__ wh,
                      const __nv_bfloat16* __restrict__ wl,
                      int OC,
                      const float* __restrict__ bias, float* __restrict__ out,
                      float* __restrict__ st_sum, float* __restrict__ st_sq) {
    extern __shared__ __align__(128) char smem[];
    constexpr int NSTAGE = (IC / 64) * 9;
    constexpr int A_LO = 18432, B_HI = 36864, B_LO = 46080, SBUF = 55296;

    const int tid = threadIdx.x, lane = tid & 31, wid = tid >> 5;
    const int wm = wid & 1, wn = wid >> 1;
    const int y  = blockIdx.x >> 1;
    const int x0 = (blockIdx.x & 1) * 128;
    const int b  = blockIdx.z;
    const int oc0 = blockIdx.y * 64;
    const uint32_t sb = smem_u32(smem);
    const __nv_bfloat16* xhb = xh + (size_t)b * HW * IC;
    const __nv_bfloat16* xlb = xl + (size_t)b * HW * IC;

    float acc[4][4][4];
    #pragma unroll
    for (int mf = 0; mf < 4; ++mf)
        #pragma unroll
        for (int nf = 0; nf < 4; ++nf)
            #pragma unroll
            for (int q = 0; q < 4; ++q) acc[mf][nf][q] = 0.f;

#define FILL(S, BO) do {                                                            \
    const int _s = (S);                                                             \
    const int _tap = (IC == 128) ? (_s >> 1) : _s;                                  \
    const int _icc = (IC == 128) ? (_s & 1) : 0;                                    \
    const int _dy = _tap / 3 - 1, _dx = _tap % 3 - 1;                               \
    const int _ys = y + _dy;                                                        \
    _Pragma("unroll")                                                               \
    for (int _k = 0; _k < 16; ++_k) {                                               \
        int _c = tid + _k * 128;                                                    \
        int _pl = _c >> 10, _r = _c & 1023;                                         \
        int _px = _r >> 3, _co = _r & 7;                                            \
        int _xs = x0 + _px + _dx;                                                   \
        bool _ok = (_ys >= 0) && (_ys < H) && (_xs >= 0) && (_xs < W);              \
        const __nv_bfloat16* _bs = _pl ? xlb : xhb;                                 \
        size_t _po = _ok ? ((size_t)_ys * W + _xs) * IC : 0;                        \
        cp_async16(sb + (BO) + _pl * A_LO + _px * 144 + _co * 16,                   \
                   (const char*)(_bs + _po) + _icc * 128 + _co * 16,                \
                   _ok ? 16u : 0u);                                                 \
    }                                                                               \
    _Pragma("unroll")                                                               \
    for (int _k = 0; _k < 8; ++_k) {                                                \
        int _c = tid + _k * 128;                                                    \
        int _pl = _c >> 9, _r = _c & 511;                                           \
        int _row = _r >> 3, _co = _r & 7;                                           \
        const __nv_bfloat16* _bs = _pl ? wl : wh;                                   \
        cp_async16(sb + (BO) + B_HI + _pl * (B_LO - B_HI) + _row * 144 + _co * 16,  \
                   (const char*)(_bs + (size_t)(_tap * OC + oc0 + _row) * IC        \
                                 + _icc * 64) + _co * 16, 16u);                     \
    }                                                                               \
} while (0)

#define COMPUTE(BO) do {                                                            \
    _Pragma("unroll")                                                               \
    for (int _ks = 0; _ks < 4; ++_ks) {                                             \
        uint32_t _ah[4][4], _al[4][4], _bh[4][2], _bl[4][2];                        \
        _Pragma("unroll")                                                           \
        for (int _mf = 0; _mf < 4; ++_mf) {                                         \
            uint32_t _a = sb + (BO) + (uint32_t)(wm * 64 + _mf * 16 + (lane & 15))  \
                          * 144 + _ks * 32 + ((lane >> 4) << 4);                    \
            ldmx4(_ah[_mf], _a);                                                    \
            ldmx4(_al[_mf], _a + A_LO);                                             \
        }                                                                           \
        _Pragma("unroll")                                                           \
        for (int _nf = 0; _nf < 4; ++_nf) {                                         \
            uint32_t _ba = sb + (BO) + B_HI                                         \
                          + (uint32_t)(wn * 32 + _nf * 8 + (lane & 7)) * 144        \
                          + _ks * 32 + (((lane >> 3) & 1) << 4);                    \
            ldmx2(_bh[_nf], _ba);                                                   \
            ldmx2(_bl[_nf], _ba + (B_LO - B_HI));                                   \
        }                                                                           \
        _Pragma("unroll")                                                           \
        for (int _mf = 0; _mf < 4; ++_mf)                                           \
            _Pragma("unroll")                                                       \
            for (int _nf = 0; _nf < 4; ++_nf) {                                     \
                mma_bf16(acc[_mf][_nf], _ah[_mf], _bh[_nf]);                        \
                mma_bf16(acc[_mf][_nf], _ah[_mf], _bl[_nf]);                        \
                mma_bf16(acc[_mf][_nf], _al[_mf], _bh[_nf]);                        \
            }                                                                       \
    }                                                                               \
} while (0)

    FILL(0, 0);
    CP_COMMIT();
    for (int s = 0; s < NSTAGE; ++s) {
        if (s + 1 < NSTAGE) {
            FILL(s + 1, ((s + 1) & 1) * SBUF);
            CP_COMMIT();
            CP_WAIT1();
        } else {
            CP_WAIT0();
        }
        __syncthreads();
        COMPUTE((s & 1) * SBUF);
        __syncthreads();
    }

#undef FILL
#undef COMPUTE

    // ---- epilogue
    float* outb = out + ((size_t)b * OC + oc0) * HW + (size_t)y * W + x0;
    const int rr0 = lane >> 2, cj = (lane & 3) * 2;

    if (MODE == 0) {
        #pragma unroll
        for (int mf = 0; mf < 4; ++mf)
            #pragma unroll
            for (int nf = 0; nf < 4; ++nf)
                #pragma unroll
                for (int q = 0; q < 4; ++q) {
                    int p   = wm * 64 + mf * 16 + rr0 + (q >> 1) * 8;
                    int ocl = wn * 32 + nf * 8 + cj + (q & 1);
                    outb[(size_t)ocl * HW + p] = acc[mf][nf][q];
                }
    } else {
        float ss[8], qq[8];
        #pragma unroll
        for (int i = 0; i < 8; ++i) { ss[i] = 0.f; qq[i] = 0.f; }
        #pragma unroll
        for (int nf = 0; nf < 4; ++nf)
            #pragma unroll
            for (int j = 0; j < 2; ++j) {
                int ocl = wn * 32 + nf * 8 + cj + j;
                float bv = __ldg(bias + oc0 + ocl);
                int idx = nf * 2 + j;
                #pragma unroll
                for (int mf = 0; mf < 4; ++mf)
                    #pragma unroll
                    for (int rr = 0; rr < 2; ++rr) {
                        float v = acc[mf][nf][rr * 2 + j] + bv;
                        int p = wm * 64 + mf * 16 + rr0 + rr * 8;
                        outb[(size_t)ocl * HW + p] = v;
                        ss[idx] += v;
                        qq[idx] += v * v;
                    }
            }
        #pragma unroll
        for (int i = 0; i < 8; ++i) {
            #pragma unroll
            for (int o = 4; o <= 16; o <<= 1) {
                ss[i] += __shfl_xor_sync(0xffffffffu, ss[i], o);
                qq[i] += __shfl_xor_sync(0xffffffffu, qq[i], o);
            }
        }
        if (lane < 4) {
            #pragma unroll
            for (int i = 0; i < 8; ++i) {
                int oc = oc0 + wn * 32 + (i >> 1) * 8 + lane * 2 + (i & 1);
                atomicAdd(&st_sum[oc], ss[i]);
                atomicAdd(&st_sq[oc], qq[i]);
            }
        }
    }
}

// ---------------- BN finalize -----------------------------------------------------
__global__ void bnfin_kernel(const float* __restrict__ sum, const float* __restrict__ sq,
                             const float* __restrict__ g, const float* __restrict__ bb,
                             float* __restrict__ scale, float* __restrict__ shift) {
    int c = threadIdx.x;
    float m = sum[c] / BN_N;
    float v = sq[c] / BN_N - m * m;
    float inv = rsqrtf(v + BN_EPS);
    float sc = g[c] * inv;
    scale[c] = sc;
    shift[c] = bb[c] - m * sc;
}

// ---------------- in-place BN + ReLU on output --------------------------------------
__global__ void final_bnrelu_kernel(float* __restrict__ out,
                                    const float* __restrict__ scale,
                                    const float* __restrict__ shift) {
    size_t idx = (size_t)blockIdx.x * blockDim.x + threadIdx.x;
    if (idx >= (size_t)BATCH * OUT_CH * HW) return;
    int c = (int)(idx >> 16) & (OUT_CH - 1);
    out[idx] = fmaxf(fmaf(out[idx], scale[c], shift[c]), 0.f);
}

// ---------------- launch -------------------------------------------------------------
extern "C" void kernel_launch(void* const* d_in, const int* in_sizes, int n_in,
                              void* d_out, int out_size) {
    const float* x1   = (const float*)d_in[0];
    const float* x2   = (const float*)d_in[1];
    const float* up_w = (const float*)d_in[2];
    const float* up_b = (const float*)d_in[3];
    const float* off_w= (const float*)d_in[4];
    const float* c1_w = (const float*)d_in[5];
    const float* c1_b = (const float*)d_in[6];
    const float* g1   = (const float*)d_in[7];
    const float* b1   = (const float*)d_in[8];
    const float* c2_w = (const float*)d_in[9];
    const float* c2_b = (const float*)d_in[10];
    const float* g2   = (const float*)d_in[11];
    const float* b2   = (const float*)d_in[12];
    float* out = (float*)d_out;

    float *up, *off, *pre1, *stats, *bn;
    __nv_bfloat16 *xch, *xcl, *xdh, *xdl, *p1h, *p1l;
    __nv_bfloat16 *woh, *wol, *w1h, *w1l, *w2h, *w2l;
    cudaGetSymbolAddress((void**)&up,    g_up);
    cudaGetSymbolAddress((void**)&off,   g_off);
    cudaGetSymbolAddress((void**)&pre1,  g_pre1);
    cudaGetSymbolAddress((void**)&stats, g_stats);
    cudaGetSymbolAddress((void**)&bn,    g_bn);
    cudaGetSymbolAddress((void**)&xch,   g_xc_h);
    cudaGetSymbolAddress((void**)&xcl,   g_xc_l);
    cudaGetSymbolAddress((void**)&xdh,   g_xd_h);
    cudaGetSymbolAddress((void**)&xdl,   g_xd_l);
    cudaGetSymbolAddress((void**)&p1h,   g_p1_h);
    cudaGetSymbolAddress((void**)&p1l,   g_p1_l);
    cudaGetSymbolAddress((void**)&woh,   g_w_off_h);
    cudaGetSymbolAddress((void**)&wol,   g_w_off_l);
    cudaGetSymbolAddress((void**)&w1h,   g_w_c1_h);
    cudaGetSymbolAddress((void**)&w1l,   g_w_c1_l);
    cudaGetSymbolAddress((void**)&w2h,   g_w_c2_h);
    cudaGetSymbolAddress((void**)&w2l,   g_w_c2_l);

    float* sum1 = stats;            float* sq1 = stats + 64;
    float* sum2 = stats + 128;      float* sq2 = stats + 192;
    float* sc1 = bn;                float* sh1 = bn + 64;
    float* sc2 = bn + 128;          float* sh2 = bn + 192;

    const int SMEM = 2 * 55296;   // 110592
    cudaFuncSetAttribute(conv_hmma_kernel<IN_CH, 0>,
                         cudaFuncAttributeMaxDynamicSharedMemorySize, SMEM);
    cudaFuncSetAttribute(conv_hmma_kernel<IN_CH, 1>,
                         cudaFuncAttributeMaxDynamicSharedMemorySize, SMEM);
    cudaFuncSetAttribute(conv_hmma_kernel<OUT_CH, 1>,
                         cudaFuncAttributeMaxDynamicSharedMemorySize, SMEM);

    // 1. pack offset weights
    {
        int n0 = 9 * OFF_CH * IN_CH;
        pack_weights_kernel<<<(n0 + 255) / 256, 256>>>(off_w, woh, wol, OFF_CH, IN_CH);
    }
    // 2. conv-transpose upsample
    upcat2_kernel<<<dim3(64, 64, BATCH), 256>>>(x1, up_w, up_b);
    // 3. concat (x2 | up) -> NHWC bf16 planes
    nchw_to_planes_kernel<<<dim3(HW / 32, IN_CH / 32, BATCH), dim3(32, 8)>>>(
        x2, up, xch, xcl, IN_CH, C1, nullptr, nullptr);
    // 4. offset conv (profiled launch): (B,128) -> (B,256)
    conv_hmma_kernel<IN_CH, 0><<<dim3(512, OFF_CH / 64, BATCH), 128, SMEM>>>(
        xch, xcl, woh, wol, OFF_CH, nullptr, off, nullptr, nullptr);
    // 5-7. remaining packs + stats init
    {
        int n1 = 9 * OUT_CH * IN_CH;
        pack_weights_kernel<<<(n1 + 255) / 256, 256>>>(c1_w, w1h, w1l, OUT_CH, IN_CH);
        int n2 = 9 * OUT_CH * OUT_CH;
        pack_weights_kernel<<<(n2 + 255) / 256, 256>>>(c2_w, w2h, w2l, OUT_CH, OUT_CH);
    }
    init_stats_kernel<<<1, 256>>>();
    // 8. deformable gather -> NHWC bf16 planes
    gather_nhwc_kernel<<<dim3(HW / 32, IN_CH / 32, BATCH), dim3(32, 8)>>>(x2);
    // 9. conv1: (B,128) -> (B,64), bias + stats
    conv_hmma_kernel<IN_CH, 1><<<dim3(512, 1, BATCH), 128, SMEM>>>(
        xdh, xdl, w1h, w1l, OUT_CH, c1_b, pre1, sum1, sq1);
    bnfin_kernel<<<1, 64>>>(sum1, sq1, g1, b1, sc1, sh1);
    // 10. pre1 -> BN+ReLU -> NHWC bf16 planes
    nchw_to_planes_kernel<<<dim3(HW / 32, OUT_CH / 32, BATCH), dim3(32, 8)>>>(
        pre1, pre1, p1h, p1l, OUT_CH, OUT_CH, sc1, sh1);
    // 11. conv2: (B,64) -> (B,64), bias + stats
    conv_hmma_kernel<OUT_CH, 1><<<dim3(512, 1, BATCH), 128, SMEM>>>(
        p1h, p1l, w2h, w2l, OUT_CH, c2_b, out, sum2, sq2);
    bnfin_kernel<<<1, 64>>>(sum2, sq2, g2, b2, sc2, sh2);
    // 12. final BN + ReLU
    {
        size_t n = (size_t)BATCH * OUT_CH * HW;
        final_bnrelu_kernel<<<(unsigned)((n + 255) / 256), 256>>>(out, sc2, sh2);
    }
}